// round 1
// baseline (speedup 1.0000x reference)
#include <cuda_runtime.h>
#include <cstdint>
#include <math.h>

#define NN 50000
#define EE 800000
#define NE 850000      // EE + NN self loops
#define D1 256         // H*DH = H*DOUT paths both 256 wide

// ---------------- scratch (device globals; no allocation allowed) ----------
__device__ int   g_is64;
__device__ int   g_src[NE];
__device__ int   g_dst[NE];
__device__ int   g_eid[NE];
__device__ int   g_deg[NN];
__device__ int   g_off[NN + 1];
__device__ int   g_cur[NN];
__device__ float g_xl[(size_t)NN * D1];
__device__ float g_xr[(size_t)NN * D1];
__device__ float g_h [(size_t)NN * D1];
__device__ float g_e [(size_t)NE * 8];

// ---------------- dtype detect: int64 edge_index has zero high words -------
__global__ void k_detect(const unsigned* __restrict__ p) {
    __shared__ unsigned acc;
    if (threadIdx.x == 0) acc = 0u;
    __syncthreads();
    unsigned v = p[threadIdx.x * 2 + 1];
    if (v) atomicOr(&acc, 1u);
    __syncthreads();
    if (threadIdx.x == 0) g_is64 = (acc == 0u) ? 1 : 0;
}

// ---------------- build src/dst with self loops ----------------------------
__global__ void k_build(const void* __restrict__ ei) {
    int i = blockIdx.x * blockDim.x + threadIdx.x;
    if (i >= NE) return;
    int s, d;
    if (i < EE) {
        if (g_is64) {
            const long long* p = (const long long*)ei;
            s = (int)p[i];
            d = (int)p[EE + i];
        } else {
            const int* p = (const int*)ei;
            s = p[i];
            d = p[EE + i];
        }
    } else {
        s = d = i - EE;
    }
    g_src[i] = s;
    g_dst[i] = d;
}

__global__ void k_zero() {
    int i = blockIdx.x * blockDim.x + threadIdx.x;
    if (i < NN) g_deg[i] = 0;
}

__global__ void k_count() {
    int i = blockIdx.x * blockDim.x + threadIdx.x;
    if (i < NE) atomicAdd(&g_deg[g_dst[i]], 1);
}

// single-block exclusive scan over 50000 counts
__global__ void k_scan() {
    const int T = 1024, CH = 49;     // 1024*49 = 50176 >= NN
    __shared__ int sm[T];
    int t = threadIdx.x;
    int beg = t * CH, end = min(beg + CH, NN);
    int s = 0;
    for (int i = beg; i < end; i++) s += g_deg[i];
    sm[t] = s;
    __syncthreads();
    for (int off = 1; off < T; off <<= 1) {
        int v = (t >= off) ? sm[t - off] : 0;
        __syncthreads();
        sm[t] += v;
        __syncthreads();
    }
    int run = sm[t] - s;            // exclusive prefix
    for (int i = beg; i < end; i++) {
        g_off[i] = run;
        g_cur[i] = run;
        run += g_deg[i];
    }
    if (t == T - 1) g_off[NN] = sm[T - 1];
}

__global__ void k_scatter() {
    int i = blockIdx.x * blockDim.x + threadIdx.x;
    if (i >= NE) return;
    int p = atomicAdd(&g_cur[g_dst[i]], 1);
    g_eid[p] = i;
}

// ---------------- SGEMM: C[N,Kc] = A[N,M] @ W[M,Kc]; 128x128x8, 8x8 micro --
__global__ void k_sgemm(const float* __restrict__ A, const float* __restrict__ W,
                        float* __restrict__ C, int N, int M, int Kc) {
    __shared__ float As[8][128];
    __shared__ float Ws[8][128];
    int t = threadIdx.x;
    int tx = t & 15, ty = t >> 4;
    int row0 = blockIdx.x * 128, col0 = blockIdx.y * 128;
    float acc[8][8];
#pragma unroll
    for (int i = 0; i < 8; i++)
#pragma unroll
        for (int j = 0; j < 8; j++) acc[i][j] = 0.f;

    for (int k0 = 0; k0 < M; k0 += 8) {
        int ar = row0 + (t >> 1);
        float4 av = make_float4(0.f, 0.f, 0.f, 0.f);
        if (ar < N) av = *(const float4*)(A + (size_t)ar * M + k0 + (t & 1) * 4);
        int kk = (t & 1) * 4, rr = t >> 1;
        As[kk + 0][rr] = av.x;
        As[kk + 1][rr] = av.y;
        As[kk + 2][rr] = av.z;
        As[kk + 3][rr] = av.w;
        *(float4*)&Ws[t >> 5][(t & 31) * 4] =
            *(const float4*)(W + (size_t)(k0 + (t >> 5)) * Kc + col0 + (t & 31) * 4);
        __syncthreads();
#pragma unroll
        for (int k = 0; k < 8; k++) {
            float a[8], b[8];
            *(float4*)(a)     = *(float4*)&As[k][ty * 8];
            *(float4*)(a + 4) = *(float4*)&As[k][ty * 8 + 4];
            *(float4*)(b)     = *(float4*)&Ws[k][tx * 8];
            *(float4*)(b + 4) = *(float4*)&Ws[k][tx * 8 + 4];
#pragma unroll
            for (int i = 0; i < 8; i++)
#pragma unroll
                for (int j = 0; j < 8; j++) acc[i][j] += a[i] * b[j];
        }
        __syncthreads();
    }
#pragma unroll
    for (int i = 0; i < 8; i++) {
        int r = row0 + ty * 8 + i;
        if (r < N) {
            float* cp = C + (size_t)r * Kc + col0 + tx * 8;
            *(float4*)cp       = make_float4(acc[i][0], acc[i][1], acc[i][2], acc[i][3]);
            *(float4*)(cp + 4) = make_float4(acc[i][4], acc[i][5], acc[i][6], acc[i][7]);
        }
    }
}

// ---------------- edge logits: one warp per edge ---------------------------
__global__ void k_logit(const float* __restrict__ xl, const float* __restrict__ xr,
                        const float* __restrict__ att, float* __restrict__ eo) {
    int w = (blockIdx.x * blockDim.x + threadIdx.x) >> 5;
    int lane = threadIdx.x & 31;
    if (w >= NE) return;
    int s = g_src[w], d = g_dst[w];
    const float* a = xl + (size_t)s * D1;
    const float* b = xr + (size_t)d * D1;
    float c[8];
#pragma unroll
    for (int k = 0; k < 8; k++) {
        float z = a[lane + 32 * k] + b[lane + 32 * k];
        z = z > 0.f ? z : 0.2f * z;            // LeakyReLU(0.2) before attention
        c[k] = z * att[k * 32 + lane];
    }
#pragma unroll
    for (int off = 16; off > 0; off >>= 1)
#pragma unroll
        for (int k = 0; k < 8; k++) c[k] += __shfl_xor_sync(0xffffffffu, c[k], off);
    if (lane == 0) {
        float* ep = eo + (size_t)w * 8;
        *(float4*)ep       = make_float4(c[0], c[1], c[2], c[3]);
        *(float4*)(ep + 4) = make_float4(c[4], c[5], c[6], c[7]);
    }
}

// ---------------- per-dst softmax + weighted aggregation -------------------
// one warp per dst node; lane l owns dims [4l..4l+3] (head l>>3) and
// [128+4l..128+4l+3] (head 4+(l>>3)).
template<int MEAN>
__global__ void k_agg(const float* __restrict__ xl, const float* __restrict__ ea,
                      const float* __restrict__ bias, float* __restrict__ out) {
    int n = (blockIdx.x * blockDim.x + threadIdx.x) >> 5;
    int lane = threadIdx.x & 31;
    if (n >= NN) return;
    int beg = g_off[n], end = g_off[n + 1];

    // per-head max / sum: lane = (slice<<3) | head
    int hh = lane & 7, sl = lane >> 3;
    float m = -1e30f;
    for (int i = beg + sl; i < end; i += 4)
        m = fmaxf(m, ea[(size_t)g_eid[i] * 8 + hh]);
    m = fmaxf(m, __shfl_xor_sync(0xffffffffu, m, 8));
    m = fmaxf(m, __shfl_xor_sync(0xffffffffu, m, 16));
    float ssum = 0.f;
    for (int i = beg + sl; i < end; i += 4)
        ssum += __expf(ea[(size_t)g_eid[i] * 8 + hh] - m);
    ssum += __shfl_xor_sync(0xffffffffu, ssum, 8);
    ssum += __shfl_xor_sync(0xffffffffu, ssum, 16);
    float inv = 1.f / (ssum + 1e-16f);

    int ha = lane >> 3;   // head of first float4; second is ha+4
    float m_a = __shfl_sync(0xffffffffu, m, ha);
    float i_a = __shfl_sync(0xffffffffu, inv, ha);
    float m_b = __shfl_sync(0xffffffffu, m, ha + 4);
    float i_b = __shfl_sync(0xffffffffu, inv, ha + 4);

    float4 acc0 = make_float4(0.f, 0.f, 0.f, 0.f);
    float4 acc1 = make_float4(0.f, 0.f, 0.f, 0.f);
    for (int i = beg; i < end; i++) {
        int ed = g_eid[i];
        int s = g_src[ed];
        float eva = ea[(size_t)ed * 8 + ha];
        float evb = ea[(size_t)ed * 8 + 4 + ha];
        float aa = __expf(eva - m_a) * i_a;
        float ab = __expf(evb - m_b) * i_b;
        const float4* xs = (const float4*)(xl + (size_t)s * D1);
        float4 v0 = xs[lane], v1 = xs[32 + lane];
        acc0.x += aa * v0.x; acc0.y += aa * v0.y; acc0.z += aa * v0.z; acc0.w += aa * v0.w;
        acc1.x += ab * v1.x; acc1.y += ab * v1.y; acc1.z += ab * v1.z; acc1.w += ab * v1.w;
    }
    if (MEAN) {
        // both float4s map to output cols 4*(lane&7)..+3; sum heads across
        // lanes {l, l^8, l^16, l^24}
        float4 tv = make_float4(acc0.x + acc1.x, acc0.y + acc1.y,
                                acc0.z + acc1.z, acc0.w + acc1.w);
#pragma unroll
        for (int off = 8; off <= 16; off <<= 1) {
            tv.x += __shfl_xor_sync(0xffffffffu, tv.x, off);
            tv.y += __shfl_xor_sync(0xffffffffu, tv.y, off);
            tv.z += __shfl_xor_sync(0xffffffffu, tv.z, off);
            tv.w += __shfl_xor_sync(0xffffffffu, tv.w, off);
        }
        if (lane < 8) {
            float4 bb = *(const float4*)(bias + lane * 4);
            float4 r = make_float4(tv.x * 0.125f + bb.x, tv.y * 0.125f + bb.y,
                                   tv.z * 0.125f + bb.z, tv.w * 0.125f + bb.w);
            *(float4*)(out + (size_t)n * 32 + lane * 4) = r;
        }
    } else {
        float4* op = (float4*)(out + (size_t)n * D1);
        op[lane] = acc0;
        op[32 + lane] = acc1;
    }
}

// ---------------- ELU + bias (layer 1 activation), in place on g_h ---------
__global__ void k_elu(const float* __restrict__ b1) {
    int i = blockIdx.x * blockDim.x + threadIdx.x;
    if (i >= NN * D1) return;
    float v = g_h[i] + b1[i & 255];
    g_h[i] = v > 0.f ? v : expm1f(v);
}

// ---------------- launch ---------------------------------------------------
extern "C" void kernel_launch(void* const* d_in, const int* in_sizes, int n_in,
                              void* d_out, int out_size) {
    const float* x    = (const float*)d_in[0];
    const void*  ei   = d_in[1];
    const float* Wl1  = (const float*)d_in[2];
    const float* Wr1  = (const float*)d_in[3];
    const float* att1 = (const float*)d_in[4];
    const float* b1   = (const float*)d_in[5];
    const float* Wl2  = (const float*)d_in[6];
    const float* Wr2  = (const float*)d_in[7];
    const float* att2 = (const float*)d_in[8];
    const float* b2   = (const float*)d_in[9];

    float *pxl, *pxr, *ph, *pe;
    cudaGetSymbolAddress((void**)&pxl, g_xl);
    cudaGetSymbolAddress((void**)&pxr, g_xr);
    cudaGetSymbolAddress((void**)&ph,  g_h);
    cudaGetSymbolAddress((void**)&pe,  g_e);

    // graph prep
    k_detect<<<1, 128>>>((const unsigned*)ei);
    k_build<<<(NE + 255) / 256, 256>>>(ei);
    k_zero<<<(NN + 255) / 256, 256>>>();
    k_count<<<(NE + 255) / 256, 256>>>();
    k_scan<<<1, 1024>>>();
    k_scatter<<<(NE + 255) / 256, 256>>>();

    dim3 gg((NN + 127) / 128, D1 / 128);
    const int lb = (NE * 32 + 255) / 256;   // warp per edge
    const int ab = (NN * 32 + 255) / 256;   // warp per dst

    // layer 1
    k_sgemm<<<gg, 256>>>(x, Wl1, pxl, NN, 128, D1);
    k_sgemm<<<gg, 256>>>(x, Wr1, pxr, NN, 128, D1);
    k_logit<<<lb, 256>>>(pxl, pxr, att1, pe);
    k_agg<0><<<ab, 256>>>(pxl, pe, nullptr, ph);
    k_elu<<<(NN * D1 + 255) / 256, 256>>>(b1);

    // layer 2
    k_sgemm<<<gg, 256>>>(ph, Wl2, pxl, NN, 256, D1);
    k_sgemm<<<gg, 256>>>(ph, Wr2, pxr, NN, 256, D1);
    k_logit<<<lb, 256>>>(pxl, pxr, att2, pe);
    k_agg<1><<<ab, 256>>>(pxl, pe, b2, (float*)d_out);
}

// round 2
// speedup vs baseline: 1.0082x; 1.0082x over previous
#include <cuda_runtime.h>
#include <cstdint>
#include <math.h>

#define NN 50000
#define EE 800000
#define NE 850000      // EE + NN self loops
#define D1 256         // H*DH = H*DOUT paths both 256 wide

// ---------------- scratch (device globals; no allocation allowed) ----------
__device__ int   g_is64;
__device__ int   g_src[NE];
__device__ int   g_dst[NE];
__device__ int   g_eid[NE];
__device__ int   g_deg[NN];
__device__ int   g_off[NN + 1];
__device__ int   g_cur[NN];
__device__ float g_xl[(size_t)NN * D1];
__device__ float g_xr[(size_t)NN * D1];
__device__ float g_h [(size_t)NN * D1];
__device__ float g_e [(size_t)NE * 8];

// ---------------- dtype detect: int64 edge_index has zero high words -------
__global__ void k_detect(const unsigned* __restrict__ p) {
    __shared__ unsigned acc;
    if (threadIdx.x == 0) acc = 0u;
    __syncthreads();
    unsigned v = p[threadIdx.x * 2 + 1];
    if (v) atomicOr(&acc, 1u);
    __syncthreads();
    if (threadIdx.x == 0) g_is64 = (acc == 0u) ? 1 : 0;
}

// ---------------- build src/dst with self loops ----------------------------
__global__ void k_build(const void* __restrict__ ei) {
    int i = blockIdx.x * blockDim.x + threadIdx.x;
    if (i >= NE) return;
    int s, d;
    if (i < EE) {
        if (g_is64) {
            const long long* p = (const long long*)ei;
            s = (int)p[i];
            d = (int)p[EE + i];
        } else {
            const int* p = (const int*)ei;
            s = p[i];
            d = p[EE + i];
        }
    } else {
        s = d = i - EE;
    }
    g_src[i] = s;
    g_dst[i] = d;
}

__global__ void k_zero() {
    int i = blockIdx.x * blockDim.x + threadIdx.x;
    if (i < NN) g_deg[i] = 0;
}

__global__ void k_count() {
    int i = blockIdx.x * blockDim.x + threadIdx.x;
    if (i < NE) atomicAdd(&g_deg[g_dst[i]], 1);
}

// single-block exclusive scan over 50000 counts
__global__ void k_scan() {
    const int T = 1024, CH = 49;     // 1024*49 = 50176 >= NN
    __shared__ int sm[T];
    int t = threadIdx.x;
    int beg = t * CH, end = min(beg + CH, NN);
    int s = 0;
    for (int i = beg; i < end; i++) s += g_deg[i];
    sm[t] = s;
    __syncthreads();
    for (int off = 1; off < T; off <<= 1) {
        int v = (t >= off) ? sm[t - off] : 0;
        __syncthreads();
        sm[t] += v;
        __syncthreads();
    }
    int run = sm[t] - s;            // exclusive prefix
    for (int i = beg; i < end; i++) {
        g_off[i] = run;
        g_cur[i] = run;
        run += g_deg[i];
    }
    if (t == T - 1) g_off[NN] = sm[T - 1];
}

__global__ void k_scatter() {
    int i = blockIdx.x * blockDim.x + threadIdx.x;
    if (i >= NE) return;
    int p = atomicAdd(&g_cur[g_dst[i]], 1);
    g_eid[p] = i;
}

// ---------------- SGEMM: C[N,Kc] = A[N,M] @ W[M,Kc]; 128x128x8, 8x8 micro --
__global__ void k_sgemm(const float* __restrict__ A, const float* __restrict__ W,
                        float* __restrict__ C, int N, int M, int Kc) {
    __shared__ float As[8][128];
    __shared__ float Ws[8][128];
    int t = threadIdx.x;
    int tx = t & 15, ty = t >> 4;
    int row0 = blockIdx.x * 128, col0 = blockIdx.y * 128;
    float acc[8][8];
#pragma unroll
    for (int i = 0; i < 8; i++)
#pragma unroll
        for (int j = 0; j < 8; j++) acc[i][j] = 0.f;

    for (int k0 = 0; k0 < M; k0 += 8) {
        int ar = row0 + (t >> 1);
        float4 av = make_float4(0.f, 0.f, 0.f, 0.f);
        if (ar < N) av = *(const float4*)(A + (size_t)ar * M + k0 + (t & 1) * 4);
        int kk = (t & 1) * 4, rr = t >> 1;
        As[kk + 0][rr] = av.x;
        As[kk + 1][rr] = av.y;
        As[kk + 2][rr] = av.z;
        As[kk + 3][rr] = av.w;
        *(float4*)&Ws[t >> 5][(t & 31) * 4] =
            *(const float4*)(W + (size_t)(k0 + (t >> 5)) * Kc + col0 + (t & 31) * 4);
        __syncthreads();
#pragma unroll
        for (int k = 0; k < 8; k++) {
            float a[8], b[8];
            *(float4*)(a)     = *(float4*)&As[k][ty * 8];
            *(float4*)(a + 4) = *(float4*)&As[k][ty * 8 + 4];
            *(float4*)(b)     = *(float4*)&Ws[k][tx * 8];
            *(float4*)(b + 4) = *(float4*)&Ws[k][tx * 8 + 4];
#pragma unroll
            for (int i = 0; i < 8; i++)
#pragma unroll
                for (int j = 0; j < 8; j++) acc[i][j] += a[i] * b[j];
        }
        __syncthreads();
    }
#pragma unroll
    for (int i = 0; i < 8; i++) {
        int r = row0 + ty * 8 + i;
        if (r < N) {
            float* cp = C + (size_t)r * Kc + col0 + tx * 8;
            *(float4*)cp       = make_float4(acc[i][0], acc[i][1], acc[i][2], acc[i][3]);
            *(float4*)(cp + 4) = make_float4(acc[i][4], acc[i][5], acc[i][6], acc[i][7]);
        }
    }
}

// ---------------- edge logits: one warp per edge ---------------------------
__global__ void k_logit(const float* __restrict__ xl, const float* __restrict__ xr,
                        const float* __restrict__ att, float* __restrict__ eo) {
    int w = (blockIdx.x * blockDim.x + threadIdx.x) >> 5;
    int lane = threadIdx.x & 31;
    if (w >= NE) return;
    int s = g_src[w], d = g_dst[w];
    const float* a = xl + (size_t)s * D1;
    const float* b = xr + (size_t)d * D1;
    float c[8];
#pragma unroll
    for (int k = 0; k < 8; k++) {
        float z = a[lane + 32 * k] + b[lane + 32 * k];
        z = z > 0.f ? z : 0.2f * z;            // LeakyReLU(0.2) before attention
        c[k] = z * att[k * 32 + lane];
    }
#pragma unroll
    for (int off = 16; off > 0; off >>= 1)
#pragma unroll
        for (int k = 0; k < 8; k++) c[k] += __shfl_xor_sync(0xffffffffu, c[k], off);
    if (lane == 0) {
        float* ep = eo + (size_t)w * 8;
        *(float4*)ep       = make_float4(c[0], c[1], c[2], c[3]);
        *(float4*)(ep + 4) = make_float4(c[4], c[5], c[6], c[7]);
    }
}

// ---------------- per-dst softmax + weighted aggregation -------------------
// one warp per dst node; lane l owns dims [4l..4l+3] (head l>>3) and
// [128+4l..128+4l+3] (head 4+(l>>3)).
template<int MEAN>
__global__ void k_agg(const float* __restrict__ xl, const float* __restrict__ ea,
                      const float* __restrict__ bias, float* __restrict__ out) {
    int n = (blockIdx.x * blockDim.x + threadIdx.x) >> 5;
    int lane = threadIdx.x & 31;
    if (n >= NN) return;
    int beg = g_off[n], end = g_off[n + 1];

    // per-head max / sum: lane = (slice<<3) | head
    int hh = lane & 7, sl = lane >> 3;
    float m = -1e30f;
    for (int i = beg + sl; i < end; i += 4)
        m = fmaxf(m, ea[(size_t)g_eid[i] * 8 + hh]);
    m = fmaxf(m, __shfl_xor_sync(0xffffffffu, m, 8));
    m = fmaxf(m, __shfl_xor_sync(0xffffffffu, m, 16));
    float ssum = 0.f;
    for (int i = beg + sl; i < end; i += 4)
        ssum += __expf(ea[(size_t)g_eid[i] * 8 + hh] - m);
    ssum += __shfl_xor_sync(0xffffffffu, ssum, 8);
    ssum += __shfl_xor_sync(0xffffffffu, ssum, 16);
    float inv = 1.f / (ssum + 1e-16f);

    int ha = lane >> 3;   // head of first float4; second is ha+4
    float m_a = __shfl_sync(0xffffffffu, m, ha);
    float i_a = __shfl_sync(0xffffffffu, inv, ha);
    float m_b = __shfl_sync(0xffffffffu, m, ha + 4);
    float i_b = __shfl_sync(0xffffffffu, inv, ha + 4);

    float4 acc0 = make_float4(0.f, 0.f, 0.f, 0.f);
    float4 acc1 = make_float4(0.f, 0.f, 0.f, 0.f);
    for (int i = beg; i < end; i++) {
        int ed = g_eid[i];
        int s = g_src[ed];
        float eva = ea[(size_t)ed * 8 + ha];
        float evb = ea[(size_t)ed * 8 + 4 + ha];
        float aa = __expf(eva - m_a) * i_a;
        float ab = __expf(evb - m_b) * i_b;
        const float4* xs = (const float4*)(xl + (size_t)s * D1);
        float4 v0 = xs[lane], v1 = xs[32 + lane];
        acc0.x += aa * v0.x; acc0.y += aa * v0.y; acc0.z += aa * v0.z; acc0.w += aa * v0.w;
        acc1.x += ab * v1.x; acc1.y += ab * v1.y; acc1.z += ab * v1.z; acc1.w += ab * v1.w;
    }
    if (MEAN) {
        // both float4s map to output cols 4*(lane&7)..+3; sum heads across
        // lanes {l, l^8, l^16, l^24}
        float4 tv = make_float4(acc0.x + acc1.x, acc0.y + acc1.y,
                                acc0.z + acc1.z, acc0.w + acc1.w);
#pragma unroll
        for (int off = 8; off <= 16; off <<= 1) {
            tv.x += __shfl_xor_sync(0xffffffffu, tv.x, off);
            tv.y += __shfl_xor_sync(0xffffffffu, tv.y, off);
            tv.z += __shfl_xor_sync(0xffffffffu, tv.z, off);
            tv.w += __shfl_xor_sync(0xffffffffu, tv.w, off);
        }
        if (lane < 8) {
            float4 bb = *(const float4*)(bias + lane * 4);
            float4 r = make_float4(tv.x * 0.125f + bb.x, tv.y * 0.125f + bb.y,
                                   tv.z * 0.125f + bb.z, tv.w * 0.125f + bb.w);
            *(float4*)(out + (size_t)n * 32 + lane * 4) = r;
        }
    } else {
        float4* op = (float4*)(out + (size_t)n * D1);
        op[lane] = acc0;
        op[32 + lane] = acc1;
    }
}

// ---------------- ELU + bias (layer 1 activation), in place on g_h ---------
__global__ void k_elu(const float* __restrict__ b1) {
    int i = blockIdx.x * blockDim.x + threadIdx.x;
    if (i >= NN * D1) return;
    float v = g_h[i] + b1[i & 255];
    g_h[i] = v > 0.f ? v : expm1f(v);
}

// ---------------- launch ---------------------------------------------------
extern "C" void kernel_launch(void* const* d_in, const int* in_sizes, int n_in,
                              void* d_out, int out_size) {
    const float* x    = (const float*)d_in[0];
    const void*  ei   = d_in[1];
    const float* Wl1  = (const float*)d_in[2];
    const float* Wr1  = (const float*)d_in[3];
    const float* att1 = (const float*)d_in[4];
    const float* b1   = (const float*)d_in[5];
    const float* Wl2  = (const float*)d_in[6];
    const float* Wr2  = (const float*)d_in[7];
    const float* att2 = (const float*)d_in[8];
    const float* b2   = (const float*)d_in[9];

    float *pxl, *pxr, *ph, *pe;
    cudaGetSymbolAddress((void**)&pxl, g_xl);
    cudaGetSymbolAddress((void**)&pxr, g_xr);
    cudaGetSymbolAddress((void**)&ph,  g_h);
    cudaGetSymbolAddress((void**)&pe,  g_e);

    // graph prep
    k_detect<<<1, 128>>>((const unsigned*)ei);
    k_build<<<(NE + 255) / 256, 256>>>(ei);
    k_zero<<<(NN + 255) / 256, 256>>>();
    k_count<<<(NE + 255) / 256, 256>>>();
    k_scan<<<1, 1024>>>();
    k_scatter<<<(NE + 255) / 256, 256>>>();

    dim3 gg((NN + 127) / 128, D1 / 128);
    const int lb = (NE * 32 + 255) / 256;   // warp per edge
    const int ab = (NN * 32 + 255) / 256;   // warp per dst

    // layer 1
    k_sgemm<<<gg, 256>>>(x, Wl1, pxl, NN, 128, D1);
    k_sgemm<<<gg, 256>>>(x, Wr1, pxr, NN, 128, D1);
    k_logit<<<lb, 256>>>(pxl, pxr, att1, pe);
    k_agg<0><<<ab, 256>>>(pxl, pe, nullptr, ph);
    k_elu<<<(NN * D1 + 255) / 256, 256>>>(b1);

    // layer 2
    k_sgemm<<<gg, 256>>>(ph, Wl2, pxl, NN, 256, D1);
    k_sgemm<<<gg, 256>>>(ph, Wr2, pxr, NN, 256, D1);
    k_logit<<<lb, 256>>>(pxl, pxr, att2, pe);
    k_agg<1><<<ab, 256>>>(pxl, pe, b2, (float*)d_out);
}

// round 3
// speedup vs baseline: 1.4341x; 1.4225x over previous
#include <cuda_runtime.h>
#include <cstdint>
#include <math.h>

#define NN 50000
#define EE 800000
#define NE 850000      // EE + NN self loops
#define D1 256         // H*DH = H*DOUT paths both 256 wide

// ---------------- scratch (device globals; no allocation allowed) ----------
__device__ int   g_is64;
__device__ int   g_src[NE];     // edge order
__device__ int   g_dst[NE];
__device__ int   g_srcp[NE];    // CSR (dst-grouped) order
__device__ int   g_dstp[NE];
__device__ int   g_deg[NN];
__device__ int   g_off[NN + 1];
__device__ int   g_cur[NN];
__device__ float g_xl[(size_t)NN * D1];
__device__ float g_xr[(size_t)NN * D1];
__device__ float g_h [(size_t)NN * D1];
__device__ float g_e [(size_t)NE * 8];

// ---------------- dtype detect: int64 edge_index has zero high words -------
__global__ void k_detect(const unsigned* __restrict__ p) {
    __shared__ unsigned acc;
    if (threadIdx.x == 0) acc = 0u;
    __syncthreads();
    unsigned v = p[threadIdx.x * 2 + 1];
    if (v) atomicOr(&acc, 1u);
    __syncthreads();
    if (threadIdx.x == 0) g_is64 = (acc == 0u) ? 1 : 0;
}

// ---------------- build src/dst with self loops ----------------------------
__global__ void k_build(const void* __restrict__ ei) {
    int i = blockIdx.x * blockDim.x + threadIdx.x;
    if (i >= NE) return;
    int s, d;
    if (i < EE) {
        if (g_is64) {
            const long long* p = (const long long*)ei;
            s = (int)p[i];
            d = (int)p[EE + i];
        } else {
            const int* p = (const int*)ei;
            s = p[i];
            d = p[EE + i];
        }
    } else {
        s = d = i - EE;
    }
    g_src[i] = s;
    g_dst[i] = d;
}

__global__ void k_zero() {
    int i = blockIdx.x * blockDim.x + threadIdx.x;
    if (i < NN) g_deg[i] = 0;
}

__global__ void k_count() {
    int i = blockIdx.x * blockDim.x + threadIdx.x;
    if (i < NE) atomicAdd(&g_deg[g_dst[i]], 1);
}

// single-block exclusive scan over 50000 counts
__global__ void k_scan() {
    const int T = 1024, CH = 49;     // 1024*49 = 50176 >= NN
    __shared__ int sm[T];
    int t = threadIdx.x;
    int beg = t * CH, end = min(beg + CH, NN);
    int s = 0;
    for (int i = beg; i < end; i++) s += g_deg[i];
    sm[t] = s;
    __syncthreads();
    for (int off = 1; off < T; off <<= 1) {
        int v = (t >= off) ? sm[t - off] : 0;
        __syncthreads();
        sm[t] += v;
        __syncthreads();
    }
    int run = sm[t] - s;            // exclusive prefix
    for (int i = beg; i < end; i++) {
        g_off[i] = run;
        g_cur[i] = run;
        run += g_deg[i];
    }
    if (t == T - 1) g_off[NN] = sm[T - 1];
}

__global__ void k_scatter() {
    int i = blockIdx.x * blockDim.x + threadIdx.x;
    if (i >= NE) return;
    int d = g_dst[i];
    int p = atomicAdd(&g_cur[d], 1);
    g_srcp[p] = g_src[i];
    g_dstp[p] = d;
}

// ---------------- tf32 tensor-core GEMM ------------------------------------
// C0 = A[N,M] @ W0[M,Kc], C1 = A @ W1 (blockIdx.y selects). 128x128 tile,
// 256 threads (8 warps as 2m x 4n, warp tile 64x32), K-chunk 32, reg prefetch.
__device__ __forceinline__ unsigned f2tf32(float x) {
    unsigned r;
    asm("cvt.rna.tf32.f32 %0, %1;" : "=r"(r) : "f"(x));
    return r;
}
__device__ __forceinline__ void mma_tf32(float* c, unsigned a0, unsigned a1,
                                         unsigned a2, unsigned a3,
                                         unsigned b0, unsigned b1) {
    asm volatile(
        "mma.sync.aligned.m16n8k8.row.col.f32.tf32.tf32.f32 "
        "{%0,%1,%2,%3}, {%4,%5,%6,%7}, {%8,%9}, {%0,%1,%2,%3};"
        : "+f"(c[0]), "+f"(c[1]), "+f"(c[2]), "+f"(c[3])
        : "r"(a0), "r"(a1), "r"(a2), "r"(a3), "r"(b0), "r"(b1));
}

__global__ __launch_bounds__(256, 1)
void k_gemm(const float* __restrict__ A,
            const float* __restrict__ W0, const float* __restrict__ W1,
            float* __restrict__ C0, float* __restrict__ C1,
            int N, int M, int Kc) {
    __shared__ unsigned As[32][132];   // [k][m] padded: conflict-free frags
    __shared__ unsigned Bs[32][132];   // [k][n]
    const int t = threadIdx.x;
    const int lane = t & 31, warp = t >> 5;
    const int wm = (warp >> 2) << 6;   // 0 / 64
    const int wn = (warp & 3) << 5;    // 0..96
    const int row0 = blockIdx.x * 128;
    int col0 = blockIdx.y * 128;
    const float* W = W0;
    float* C = C0;
    if (col0 >= Kc) { col0 -= Kc; W = W1; C = C1; }

    float acc[4][4][4];
#pragma unroll
    for (int mt = 0; mt < 4; mt++)
#pragma unroll
        for (int nt = 0; nt < 4; nt++)
#pragma unroll
            for (int j = 0; j < 4; j++) acc[mt][nt][j] = 0.f;

    const int arow = t >> 1;             // 0..127
    const int akq  = (t & 1) * 16;       // 0 / 16 float offset within chunk
    const int brow = t >> 3;             // 0..31 (k)
    const int bql  = (t & 7) * 4;        // n offset, +32 per q
    const bool aok = (row0 + arow) < N;

    float4 aR[4], bR[4];
    {   // prefetch chunk 0
        const float* ap = A + (size_t)(row0 + arow) * M + akq;
#pragma unroll
        for (int q = 0; q < 4; q++)
            aR[q] = aok ? *(const float4*)(ap + q * 4)
                        : make_float4(0.f, 0.f, 0.f, 0.f);
        const float* bp = W + (size_t)brow * Kc + col0 + bql;
#pragma unroll
        for (int q = 0; q < 4; q++)
            bR[q] = *(const float4*)(bp + q * 32);
    }

    const int nchunk = M >> 5;
    for (int ch = 0; ch < nchunk; ch++) {
#pragma unroll
        for (int q = 0; q < 4; q++) {
            int k = akq + q * 4;
            As[k + 0][arow] = f2tf32(aR[q].x);
            As[k + 1][arow] = f2tf32(aR[q].y);
            As[k + 2][arow] = f2tf32(aR[q].z);
            As[k + 3][arow] = f2tf32(aR[q].w);
        }
#pragma unroll
        for (int q = 0; q < 4; q++) {
            int n = bql + q * 32;
            Bs[brow][n + 0] = f2tf32(bR[q].x);
            Bs[brow][n + 1] = f2tf32(bR[q].y);
            Bs[brow][n + 2] = f2tf32(bR[q].z);
            Bs[brow][n + 3] = f2tf32(bR[q].w);
        }
        __syncthreads();
        if (ch + 1 < nchunk) {          // prefetch next chunk into regs
            int k0 = (ch + 1) << 5;
            const float* ap = A + (size_t)(row0 + arow) * M + k0 + akq;
#pragma unroll
            for (int q = 0; q < 4; q++)
                aR[q] = aok ? *(const float4*)(ap + q * 4)
                            : make_float4(0.f, 0.f, 0.f, 0.f);
            const float* bp = W + (size_t)(k0 + brow) * Kc + col0 + bql;
#pragma unroll
            for (int q = 0; q < 4; q++)
                bR[q] = *(const float4*)(bp + q * 32);
        }
        const int r = lane >> 2, c = lane & 3;
#pragma unroll
        for (int ks = 0; ks < 4; ks++) {
            int k = ks * 8;
            unsigned a[4][4], b[4][2];
#pragma unroll
            for (int mt = 0; mt < 4; mt++) {
                int mb = wm + mt * 16 + r;
                a[mt][0] = As[k + c][mb];
                a[mt][1] = As[k + c][mb + 8];
                a[mt][2] = As[k + c + 4][mb];
                a[mt][3] = As[k + c + 4][mb + 8];
            }
#pragma unroll
            for (int nt = 0; nt < 4; nt++) {
                int nb = wn + nt * 8 + r;
                b[nt][0] = Bs[k + c][nb];
                b[nt][1] = Bs[k + c + 4][nb];
            }
#pragma unroll
            for (int mt = 0; mt < 4; mt++)
#pragma unroll
                for (int nt = 0; nt < 4; nt++)
                    mma_tf32(acc[mt][nt], a[mt][0], a[mt][1], a[mt][2],
                             a[mt][3], b[nt][0], b[nt][1]);
        }
        __syncthreads();
    }
    // epilogue
    const int r = lane >> 2, c2 = (lane & 3) * 2;
#pragma unroll
    for (int mt = 0; mt < 4; mt++) {
#pragma unroll
        for (int half = 0; half < 2; half++) {
            int row = row0 + wm + mt * 16 + r + half * 8;
            if (row < N) {
#pragma unroll
                for (int nt = 0; nt < 4; nt++) {
                    float2 v = half
                        ? make_float2(acc[mt][nt][2], acc[mt][nt][3])
                        : make_float2(acc[mt][nt][0], acc[mt][nt][1]);
                    *(float2*)(C + (size_t)row * Kc + col0 + wn + nt * 8 + c2) = v;
                }
            }
        }
    }
}

// ---------------- edge logits: one warp per CSR position -------------------
__global__ void k_logit(const float* __restrict__ xl, const float* __restrict__ xr,
                        const float* __restrict__ att, float* __restrict__ eo) {
    int w = (blockIdx.x * blockDim.x + threadIdx.x) >> 5;
    int lane = threadIdx.x & 31;
    if (w >= NE) return;
    int s = g_srcp[w], d = g_dstp[w];
    const float* a = xl + (size_t)s * D1;
    const float* b = xr + (size_t)d * D1;
    float c[8];
#pragma unroll
    for (int k = 0; k < 8; k++) {
        float z = a[lane + 32 * k] + b[lane + 32 * k];
        z = z > 0.f ? z : 0.2f * z;            // LeakyReLU(0.2) before attention
        c[k] = z * att[k * 32 + lane];
    }
#pragma unroll
    for (int off = 16; off > 0; off >>= 1)
#pragma unroll
        for (int k = 0; k < 8; k++) c[k] += __shfl_xor_sync(0xffffffffu, c[k], off);
    if (lane == 0) {
        float* ep = eo + (size_t)w * 8;
        *(float4*)ep       = make_float4(c[0], c[1], c[2], c[3]);
        *(float4*)(ep + 4) = make_float4(c[4], c[5], c[6], c[7]);
    }
}

// ---------------- per-dst softmax + weighted aggregation -------------------
// one warp per dst node. MODE 0: write 256-wide h with fused bias+ELU.
// MODE 1: head-mean + bias, write 32-wide output.
template<int MODE>
__global__ void k_agg(const float* __restrict__ xl, const float* __restrict__ ea,
                      const float* __restrict__ bias, float* __restrict__ out) {
    int n = (blockIdx.x * blockDim.x + threadIdx.x) >> 5;
    int lane = threadIdx.x & 31;
    if (n >= NN) return;
    int beg = g_off[n], end = g_off[n + 1];

    // per-head max / sum: lane = (slice<<3) | head
    int hh = lane & 7, sl = lane >> 3;
    float m = -1e30f;
    for (int i = beg + sl; i < end; i += 4)
        m = fmaxf(m, ea[(size_t)i * 8 + hh]);
    m = fmaxf(m, __shfl_xor_sync(0xffffffffu, m, 8));
    m = fmaxf(m, __shfl_xor_sync(0xffffffffu, m, 16));
    float ssum = 0.f;
    for (int i = beg + sl; i < end; i += 4)
        ssum += __expf(ea[(size_t)i * 8 + hh] - m);
    ssum += __shfl_xor_sync(0xffffffffu, ssum, 8);
    ssum += __shfl_xor_sync(0xffffffffu, ssum, 16);
    float inv = 1.f / (ssum + 1e-16f);

    int ha = lane >> 3;   // head of first float4; second float4 is head ha+4
    float m_a = __shfl_sync(0xffffffffu, m, ha);
    float i_a = __shfl_sync(0xffffffffu, inv, ha);
    float m_b = __shfl_sync(0xffffffffu, m, ha + 4);
    float i_b = __shfl_sync(0xffffffffu, inv, ha + 4);

    float4 acc0 = make_float4(0.f, 0.f, 0.f, 0.f);
    float4 acc1 = make_float4(0.f, 0.f, 0.f, 0.f);
    for (int i = beg; i < end; i++) {
        int s = g_srcp[i];
        float eva = ea[(size_t)i * 8 + ha];
        float evb = ea[(size_t)i * 8 + 4 + ha];
        float aa = __expf(eva - m_a) * i_a;
        float ab = __expf(evb - m_b) * i_b;
        const float4* xs = (const float4*)(xl + (size_t)s * D1);
        float4 v0 = xs[lane], v1 = xs[32 + lane];
        acc0.x += aa * v0.x; acc0.y += aa * v0.y; acc0.z += aa * v0.z; acc0.w += aa * v0.w;
        acc1.x += ab * v1.x; acc1.y += ab * v1.y; acc1.z += ab * v1.z; acc1.w += ab * v1.w;
    }
    if (MODE == 1) {
        // both float4s map to output cols 4*(lane&7)..+3; sum heads across
        // lanes {l, l^8, l^16, l^24}
        float4 tv = make_float4(acc0.x + acc1.x, acc0.y + acc1.y,
                                acc0.z + acc1.z, acc0.w + acc1.w);
#pragma unroll
        for (int off = 8; off <= 16; off <<= 1) {
            tv.x += __shfl_xor_sync(0xffffffffu, tv.x, off);
            tv.y += __shfl_xor_sync(0xffffffffu, tv.y, off);
            tv.z += __shfl_xor_sync(0xffffffffu, tv.z, off);
            tv.w += __shfl_xor_sync(0xffffffffu, tv.w, off);
        }
        if (lane < 8) {
            float4 bb = *(const float4*)(bias + lane * 4);
            float4 r = make_float4(tv.x * 0.125f + bb.x, tv.y * 0.125f + bb.y,
                                   tv.z * 0.125f + bb.z, tv.w * 0.125f + bb.w);
            *(float4*)(out + (size_t)n * 32 + lane * 4) = r;
        }
    } else {
        // fused bias + ELU for layer 1 hidden state
        float4 b0 = *(const float4*)(bias + lane * 4);
        float4 b1 = *(const float4*)(bias + 128 + lane * 4);
        float4 r0, r1;
        float v;
        v = acc0.x + b0.x; r0.x = v > 0.f ? v : expm1f(v);
        v = acc0.y + b0.y; r0.y = v > 0.f ? v : expm1f(v);
        v = acc0.z + b0.z; r0.z = v > 0.f ? v : expm1f(v);
        v = acc0.w + b0.w; r0.w = v > 0.f ? v : expm1f(v);
        v = acc1.x + b1.x; r1.x = v > 0.f ? v : expm1f(v);
        v = acc1.y + b1.y; r1.y = v > 0.f ? v : expm1f(v);
        v = acc1.z + b1.z; r1.z = v > 0.f ? v : expm1f(v);
        v = acc1.w + b1.w; r1.w = v > 0.f ? v : expm1f(v);
        float4* op = (float4*)(out + (size_t)n * D1);
        op[lane] = r0;
        op[32 + lane] = r1;
    }
}

// ---------------- launch ---------------------------------------------------
extern "C" void kernel_launch(void* const* d_in, const int* in_sizes, int n_in,
                              void* d_out, int out_size) {
    const float* x    = (const float*)d_in[0];
    const void*  ei   = d_in[1];
    const float* Wl1  = (const float*)d_in[2];
    const float* Wr1  = (const float*)d_in[3];
    const float* att1 = (const float*)d_in[4];
    const float* b1   = (const float*)d_in[5];
    const float* Wl2  = (const float*)d_in[6];
    const float* Wr2  = (const float*)d_in[7];
    const float* att2 = (const float*)d_in[8];
    const float* b2   = (const float*)d_in[9];

    float *pxl, *pxr, *ph, *pe;
    cudaGetSymbolAddress((void**)&pxl, g_xl);
    cudaGetSymbolAddress((void**)&pxr, g_xr);
    cudaGetSymbolAddress((void**)&ph,  g_h);
    cudaGetSymbolAddress((void**)&pe,  g_e);

    // graph prep
    k_detect<<<1, 128>>>((const unsigned*)ei);
    k_build<<<(NE + 255) / 256, 256>>>(ei);
    k_zero<<<(NN + 255) / 256, 256>>>();
    k_count<<<(NE + 255) / 256, 256>>>();
    k_scan<<<1, 1024>>>();
    k_scatter<<<(NE + 255) / 256, 256>>>();

    dim3 gg((NN + 127) / 128, 2 * D1 / 128);   // both Wl and Wr outputs
    const int lb = (NE * 32 + 255) / 256;      // warp per edge (CSR order)
    const int ab = (NN * 32 + 255) / 256;      // warp per dst

    // layer 1
    k_gemm<<<gg, 256>>>(x, Wl1, Wr1, pxl, pxr, NN, 128, D1);
    k_logit<<<lb, 256>>>(pxl, pxr, att1, pe);
    k_agg<0><<<ab, 256>>>(pxl, pe, b1, ph);

    // layer 2
    k_gemm<<<gg, 256>>>(ph, Wl2, Wr2, pxl, pxr, NN, 256, D1);
    k_logit<<<lb, 256>>>(pxl, pxr, att2, pe);
    k_agg<1><<<ab, 256>>>(pxl, pe, b2, (float*)d_out);
}

// round 4
// speedup vs baseline: 2.2073x; 1.5391x over previous
#include <cuda_runtime.h>
#include <cstdint>
#include <math.h>

#define NN 50000
#define EE 800000
#define NE 850000      // EE + NN self loops
#define D1 256         // H*DH = H*DOUT paths both 256 wide

// ---------------- scratch (device globals; no allocation allowed) ----------
__device__ int   g_is64;
__device__ int   g_src[NE];     // edge order
__device__ int   g_dst[NE];
__device__ int   g_srcp[NE];    // CSR (dst-grouped) order
__device__ int   g_deg[NN];
__device__ int   g_off[NN + 1];
__device__ int   g_cur[NN];
__device__ float g_xl[(size_t)NN * D1];
__device__ float g_xr[(size_t)NN * D1];
__device__ float g_h [(size_t)NN * D1];

// ---------------- dtype detect: int64 edge_index has zero high words -------
__global__ void k_detect(const unsigned* __restrict__ p) {
    __shared__ unsigned acc;
    if (threadIdx.x == 0) acc = 0u;
    __syncthreads();
    unsigned v = p[threadIdx.x * 2 + 1];
    if (v) atomicOr(&acc, 1u);
    __syncthreads();
    if (threadIdx.x == 0) g_is64 = (acc == 0u) ? 1 : 0;
}

// ---------------- build src/dst with self loops ----------------------------
__global__ void k_build(const void* __restrict__ ei) {
    int i = blockIdx.x * blockDim.x + threadIdx.x;
    if (i >= NE) return;
    int s, d;
    if (i < EE) {
        if (g_is64) {
            const long long* p = (const long long*)ei;
            s = (int)p[i];
            d = (int)p[EE + i];
        } else {
            const int* p = (const int*)ei;
            s = p[i];
            d = p[EE + i];
        }
    } else {
        s = d = i - EE;
    }
    g_src[i] = s;
    g_dst[i] = d;
}

__global__ void k_zero() {
    int i = blockIdx.x * blockDim.x + threadIdx.x;
    if (i < NN) g_deg[i] = 0;
}

__global__ void k_count() {
    int i = blockIdx.x * blockDim.x + threadIdx.x;
    if (i < NE) atomicAdd(&g_deg[g_dst[i]], 1);
}

// single-block exclusive scan over 50000 counts
__global__ void k_scan() {
    const int T = 1024, CH = 49;     // 1024*49 = 50176 >= NN
    __shared__ int sm[T];
    int t = threadIdx.x;
    int beg = t * CH, end = min(beg + CH, NN);
    int s = 0;
    for (int i = beg; i < end; i++) s += g_deg[i];
    sm[t] = s;
    __syncthreads();
    for (int off = 1; off < T; off <<= 1) {
        int v = (t >= off) ? sm[t - off] : 0;
        __syncthreads();
        sm[t] += v;
        __syncthreads();
    }
    int run = sm[t] - s;            // exclusive prefix
    for (int i = beg; i < end; i++) {
        g_off[i] = run;
        g_cur[i] = run;
        run += g_deg[i];
    }
    if (t == T - 1) g_off[NN] = sm[T - 1];
}

__global__ void k_scatter() {
    int i = blockIdx.x * blockDim.x + threadIdx.x;
    if (i >= NE) return;
    int p = atomicAdd(&g_cur[g_dst[i]], 1);
    g_srcp[p] = g_src[i];
}

// ---------------- tf32 tensor-core GEMM ------------------------------------
// C0 = A[N,M] @ W0[M,Kc], C1 = A @ W1 (blockIdx.y selects). 128x128 tile,
// 256 threads (8 warps as 2m x 4n, warp tile 64x32), K-chunk 32, reg prefetch.
__device__ __forceinline__ unsigned f2tf32(float x) {
    unsigned r;
    asm("cvt.rna.tf32.f32 %0, %1;" : "=r"(r) : "f"(x));
    return r;
}
__device__ __forceinline__ void mma_tf32(float* c, unsigned a0, unsigned a1,
                                         unsigned a2, unsigned a3,
                                         unsigned b0, unsigned b1) {
    asm volatile(
        "mma.sync.aligned.m16n8k8.row.col.f32.tf32.tf32.f32 "
        "{%0,%1,%2,%3}, {%4,%5,%6,%7}, {%8,%9}, {%0,%1,%2,%3};"
        : "+f"(c[0]), "+f"(c[1]), "+f"(c[2]), "+f"(c[3])
        : "r"(a0), "r"(a1), "r"(a2), "r"(a3), "r"(b0), "r"(b1));
}

__global__ __launch_bounds__(256, 1)
void k_gemm(const float* __restrict__ A,
            const float* __restrict__ W0, const float* __restrict__ W1,
            float* __restrict__ C0, float* __restrict__ C1,
            int N, int M, int Kc) {
    __shared__ unsigned As[32][132];   // [k][m] padded: conflict-free frags
    __shared__ unsigned Bs[32][132];   // [k][n]
    const int t = threadIdx.x;
    const int lane = t & 31, warp = t >> 5;
    const int wm = (warp >> 2) << 6;   // 0 / 64
    const int wn = (warp & 3) << 5;    // 0..96
    const int row0 = blockIdx.x * 128;
    int col0 = blockIdx.y * 128;
    const float* W = W0;
    float* C = C0;
    if (col0 >= Kc) { col0 -= Kc; W = W1; C = C1; }

    float acc[4][4][4];
#pragma unroll
    for (int mt = 0; mt < 4; mt++)
#pragma unroll
        for (int nt = 0; nt < 4; nt++)
#pragma unroll
            for (int j = 0; j < 4; j++) acc[mt][nt][j] = 0.f;

    const int arow = t >> 1;             // 0..127
    const int akq  = (t & 1) * 16;       // 0 / 16 float offset within chunk
    const int brow = t >> 3;             // 0..31 (k)
    const int bql  = (t & 7) * 4;        // n offset, +32 per q
    const bool aok = (row0 + arow) < N;

    float4 aR[4], bR[4];
    {   // prefetch chunk 0
        const float* ap = A + (size_t)(row0 + arow) * M + akq;
#pragma unroll
        for (int q = 0; q < 4; q++)
            aR[q] = aok ? *(const float4*)(ap + q * 4)
                        : make_float4(0.f, 0.f, 0.f, 0.f);
        const float* bp = W + (size_t)brow * Kc + col0 + bql;
#pragma unroll
        for (int q = 0; q < 4; q++)
            bR[q] = *(const float4*)(bp + q * 32);
    }

    const int nchunk = M >> 5;
    for (int ch = 0; ch < nchunk; ch++) {
#pragma unroll
        for (int q = 0; q < 4; q++) {
            int k = akq + q * 4;
            As[k + 0][arow] = f2tf32(aR[q].x);
            As[k + 1][arow] = f2tf32(aR[q].y);
            As[k + 2][arow] = f2tf32(aR[q].z);
            As[k + 3][arow] = f2tf32(aR[q].w);
        }
#pragma unroll
        for (int q = 0; q < 4; q++) {
            int n = bql + q * 32;
            Bs[brow][n + 0] = f2tf32(bR[q].x);
            Bs[brow][n + 1] = f2tf32(bR[q].y);
            Bs[brow][n + 2] = f2tf32(bR[q].z);
            Bs[brow][n + 3] = f2tf32(bR[q].w);
        }
        __syncthreads();
        if (ch + 1 < nchunk) {          // prefetch next chunk into regs
            int k0 = (ch + 1) << 5;
            const float* ap = A + (size_t)(row0 + arow) * M + k0 + akq;
#pragma unroll
            for (int q = 0; q < 4; q++)
                aR[q] = aok ? *(const float4*)(ap + q * 4)
                            : make_float4(0.f, 0.f, 0.f, 0.f);
            const float* bp = W + (size_t)(k0 + brow) * Kc + col0 + bql;
#pragma unroll
            for (int q = 0; q < 4; q++)
                bR[q] = *(const float4*)(bp + q * 32);
        }
        const int r = lane >> 2, c = lane & 3;
#pragma unroll
        for (int ks = 0; ks < 4; ks++) {
            int k = ks * 8;
            unsigned a[4][4], b[4][2];
#pragma unroll
            for (int mt = 0; mt < 4; mt++) {
                int mb = wm + mt * 16 + r;
                a[mt][0] = As[k + c][mb];
                a[mt][1] = As[k + c][mb + 8];
                a[mt][2] = As[k + c + 4][mb];
                a[mt][3] = As[k + c + 4][mb + 8];
            }
#pragma unroll
            for (int nt = 0; nt < 4; nt++) {
                int nb = wn + nt * 8 + r;
                b[nt][0] = Bs[k + c][nb];
                b[nt][1] = Bs[k + c + 4][nb];
            }
#pragma unroll
            for (int mt = 0; mt < 4; mt++)
#pragma unroll
                for (int nt = 0; nt < 4; nt++)
                    mma_tf32(acc[mt][nt], a[mt][0], a[mt][1], a[mt][2],
                             a[mt][3], b[nt][0], b[nt][1]);
        }
        __syncthreads();
    }
    // epilogue
    const int r = lane >> 2, c2 = (lane & 3) * 2;
#pragma unroll
    for (int mt = 0; mt < 4; mt++) {
#pragma unroll
        for (int half = 0; half < 2; half++) {
            int row = row0 + wm + mt * 16 + r + half * 8;
            if (row < N) {
#pragma unroll
                for (int nt = 0; nt < 4; nt++) {
                    float2 v = half
                        ? make_float2(acc[mt][nt][2], acc[mt][nt][3])
                        : make_float2(acc[mt][nt][0], acc[mt][nt][1]);
                    *(float2*)(C + (size_t)row * Kc + col0 + wn + nt * 8 + c2) = v;
                }
            }
        }
    }
}

// ---------------- fused GATv2 edge pass: logit + online softmax + agg ------
// One warp per dst node. Lane l owns dims [4l..4l+3] (head hA=l>>3) in float4
// A and dims [128+4l..128+4l+3] (head hA+4) in float4 B. Per edge: read
// xl[src] once, logit via in-register dot + 8-lane butterfly, online-softmax
// rescale of accumulators. MODE 0: bias+ELU, write 256-wide h.
// MODE 1: head-mean + bias, write 32-wide output.
template<int MODE>
__global__ void k_fused(const float* __restrict__ xl, const float* __restrict__ xr,
                        const float* __restrict__ att, const float* __restrict__ bias,
                        float* __restrict__ out) {
    int n = (blockIdx.x * blockDim.x + threadIdx.x) >> 5;
    int lane = threadIdx.x & 31;
    if (n >= NN) return;
    int beg = g_off[n], end = g_off[n + 1];

    // per-dst target transform + attention vector slices (register resident)
    const float4* xrp = (const float4*)(xr + (size_t)n * D1);
    float4 r0 = xrp[lane], r1 = xrp[32 + lane];
    float4 atA = *(const float4*)(att + 4 * lane);
    float4 atB = *(const float4*)(att + 128 + 4 * lane);

    float mA = -1e30f, mB = -1e30f, sA = 0.f, sB = 0.f;
    float4 acc0 = make_float4(0.f, 0.f, 0.f, 0.f);
    float4 acc1 = make_float4(0.f, 0.f, 0.f, 0.f);

    for (int i = beg; i < end; i++) {
        int s = __ldg(&g_srcp[i]);
        const float4* xs = (const float4*)(xl + (size_t)s * D1);
        float4 v0 = xs[lane], v1 = xs[32 + lane];
        // GATv2 logit contribution: leakyrelu(xl+xr) . att
        float z, cA, cB;
        z = v0.x + r0.x; z = z > 0.f ? z : 0.2f * z; cA  = z * atA.x;
        z = v0.y + r0.y; z = z > 0.f ? z : 0.2f * z; cA += z * atA.y;
        z = v0.z + r0.z; z = z > 0.f ? z : 0.2f * z; cA += z * atA.z;
        z = v0.w + r0.w; z = z > 0.f ? z : 0.2f * z; cA += z * atA.w;
        z = v1.x + r1.x; z = z > 0.f ? z : 0.2f * z; cB  = z * atB.x;
        z = v1.y + r1.y; z = z > 0.f ? z : 0.2f * z; cB += z * atB.y;
        z = v1.z + r1.z; z = z > 0.f ? z : 0.2f * z; cB += z * atB.z;
        z = v1.w + r1.w; z = z > 0.f ? z : 0.2f * z; cB += z * atB.w;
        // reduce within each 8-lane head group
#pragma unroll
        for (int off = 1; off < 8; off <<= 1) {
            cA += __shfl_xor_sync(0xffffffffu, cA, off);
            cB += __shfl_xor_sync(0xffffffffu, cB, off);
        }
        // online softmax update (head A)
        float mAn = fmaxf(mA, cA);
        float scA = __expf(mA - mAn);
        float pA  = __expf(cA - mAn);
        sA = sA * scA + pA;
        acc0.x = acc0.x * scA + pA * v0.x;
        acc0.y = acc0.y * scA + pA * v0.y;
        acc0.z = acc0.z * scA + pA * v0.z;
        acc0.w = acc0.w * scA + pA * v0.w;
        mA = mAn;
        // head B
        float mBn = fmaxf(mB, cB);
        float scB = __expf(mB - mBn);
        float pB  = __expf(cB - mBn);
        sB = sB * scB + pB;
        acc1.x = acc1.x * scB + pB * v1.x;
        acc1.y = acc1.y * scB + pB * v1.y;
        acc1.z = acc1.z * scB + pB * v1.z;
        acc1.w = acc1.w * scB + pB * v1.w;
        mB = mBn;
    }
    float iA = 1.f / (sA + 1e-16f);
    float iB = 1.f / (sB + 1e-16f);
    acc0.x *= iA; acc0.y *= iA; acc0.z *= iA; acc0.w *= iA;
    acc1.x *= iB; acc1.y *= iB; acc1.z *= iB; acc1.w *= iB;

    if (MODE == 1) {
        // head-mean: both float4s map to output cols 4*(lane&7)..+3; sum
        // heads across lanes {l, l^8, l^16, l^24}
        float4 tv = make_float4(acc0.x + acc1.x, acc0.y + acc1.y,
                                acc0.z + acc1.z, acc0.w + acc1.w);
#pragma unroll
        for (int off = 8; off <= 16; off <<= 1) {
            tv.x += __shfl_xor_sync(0xffffffffu, tv.x, off);
            tv.y += __shfl_xor_sync(0xffffffffu, tv.y, off);
            tv.z += __shfl_xor_sync(0xffffffffu, tv.z, off);
            tv.w += __shfl_xor_sync(0xffffffffu, tv.w, off);
        }
        if (lane < 8) {
            float4 bb = *(const float4*)(bias + lane * 4);
            float4 r = make_float4(tv.x * 0.125f + bb.x, tv.y * 0.125f + bb.y,
                                   tv.z * 0.125f + bb.z, tv.w * 0.125f + bb.w);
            *(float4*)(out + (size_t)n * 32 + lane * 4) = r;
        }
    } else {
        // fused bias + ELU for layer 1 hidden state
        float4 b0 = *(const float4*)(bias + lane * 4);
        float4 b1 = *(const float4*)(bias + 128 + lane * 4);
        float4 w0, w1;
        float v;
        v = acc0.x + b0.x; w0.x = v > 0.f ? v : expm1f(v);
        v = acc0.y + b0.y; w0.y = v > 0.f ? v : expm1f(v);
        v = acc0.z + b0.z; w0.z = v > 0.f ? v : expm1f(v);
        v = acc0.w + b0.w; w0.w = v > 0.f ? v : expm1f(v);
        v = acc1.x + b1.x; w1.x = v > 0.f ? v : expm1f(v);
        v = acc1.y + b1.y; w1.y = v > 0.f ? v : expm1f(v);
        v = acc1.z + b1.z; w1.z = v > 0.f ? v : expm1f(v);
        v = acc1.w + b1.w; w1.w = v > 0.f ? v : expm1f(v);
        float4* op = (float4*)(out + (size_t)n * D1);
        op[lane] = w0;
        op[32 + lane] = w1;
    }
}

// ---------------- launch ---------------------------------------------------
extern "C" void kernel_launch(void* const* d_in, const int* in_sizes, int n_in,
                              void* d_out, int out_size) {
    const float* x    = (const float*)d_in[0];
    const void*  ei   = d_in[1];
    const float* Wl1  = (const float*)d_in[2];
    const float* Wr1  = (const float*)d_in[3];
    const float* att1 = (const float*)d_in[4];
    const float* b1   = (const float*)d_in[5];
    const float* Wl2  = (const float*)d_in[6];
    const float* Wr2  = (const float*)d_in[7];
    const float* att2 = (const float*)d_in[8];
    const float* b2   = (const float*)d_in[9];

    float *pxl, *pxr, *ph;
    cudaGetSymbolAddress((void**)&pxl, g_xl);
    cudaGetSymbolAddress((void**)&pxr, g_xr);
    cudaGetSymbolAddress((void**)&ph,  g_h);

    // graph prep
    k_detect<<<1, 128>>>((const unsigned*)ei);
    k_build<<<(NE + 255) / 256, 256>>>(ei);
    k_zero<<<(NN + 255) / 256, 256>>>();
    k_count<<<(NE + 255) / 256, 256>>>();
    k_scan<<<1, 1024>>>();
    k_scatter<<<(NE + 255) / 256, 256>>>();

    dim3 gg((NN + 127) / 128, 2 * D1 / 128);   // both Wl and Wr outputs
    const int ab = (NN * 32 + 255) / 256;      // warp per dst

    // layer 1
    k_gemm<<<gg, 256>>>(x, Wl1, Wr1, pxl, pxr, NN, 128, D1);
    k_fused<0><<<ab, 256>>>(pxl, pxr, att1, b1, ph);

    // layer 2
    k_gemm<<<gg, 256>>>(ph, Wl2, Wr2, pxl, pxr, NN, 256, D1);
    k_fused<1><<<ab, 256>>>(pxl, pxr, att2, b2, (float*)d_out);
}

// round 5
// speedup vs baseline: 2.2956x; 1.0400x over previous
#include <cuda_runtime.h>
#include <cstdint>
#include <math.h>

#define NN 50000
#define EE 800000
#define NE 850000      // EE + NN self loops
#define D1 256         // H*DH = H*DOUT paths both 256 wide

// ---------------- scratch (device globals; no allocation allowed) ----------
__device__ int   g_is64;
__device__ int   g_src[NE];     // edge order
__device__ int   g_dst[NE];
__device__ int   g_srcp[NE];    // CSR (dst-grouped) order
__device__ int   g_deg[NN];
__device__ int   g_off[NN + 1];
__device__ int   g_cur[NN];
__device__ float g_xl[(size_t)NN * D1];
__device__ float g_xr[(size_t)NN * D1];
__device__ float g_h [(size_t)NN * D1];

// ---------------- detect dtype (block 0) + zero degree array ---------------
__global__ void k_detect_zero(const unsigned* __restrict__ p) {
    int i = blockIdx.x * blockDim.x + threadIdx.x;
    if (i < NN) g_deg[i] = 0;
    if (blockIdx.x == 0) {
        __shared__ unsigned acc;
        if (threadIdx.x == 0) acc = 0u;
        __syncthreads();
        if (threadIdx.x < 128) {
            unsigned v = p[threadIdx.x * 2 + 1];
            if (v) atomicOr(&acc, 1u);
        }
        __syncthreads();
        if (threadIdx.x == 0) g_is64 = (acc == 0u) ? 1 : 0;
    }
}

// ---------------- build src/dst with self loops + degree count -------------
__global__ void k_build_count(const void* __restrict__ ei) {
    int i = blockIdx.x * blockDim.x + threadIdx.x;
    if (i >= NE) return;
    int s, d;
    if (i < EE) {
        if (g_is64) {
            const long long* p = (const long long*)ei;
            s = (int)p[i];
            d = (int)p[EE + i];
        } else {
            const int* p = (const int*)ei;
            s = p[i];
            d = p[EE + i];
        }
    } else {
        s = d = i - EE;
    }
    g_src[i] = s;
    g_dst[i] = d;
    atomicAdd(&g_deg[d], 1);
}

// single-block exclusive scan over 50000 counts
__global__ void k_scan() {
    const int T = 1024, CH = 49;     // 1024*49 = 50176 >= NN
    __shared__ int sm[T];
    int t = threadIdx.x;
    int beg = t * CH, end = min(beg + CH, NN);
    int s = 0;
    for (int i = beg; i < end; i++) s += g_deg[i];
    sm[t] = s;
    __syncthreads();
    for (int off = 1; off < T; off <<= 1) {
        int v = (t >= off) ? sm[t - off] : 0;
        __syncthreads();
        sm[t] += v;
        __syncthreads();
    }
    int run = sm[t] - s;            // exclusive prefix
    for (int i = beg; i < end; i++) {
        g_off[i] = run;
        g_cur[i] = run;
        run += g_deg[i];
    }
    if (t == T - 1) g_off[NN] = sm[T - 1];
}

__global__ void k_scatter() {
    int i = blockIdx.x * blockDim.x + threadIdx.x;
    if (i >= NE) return;
    int p = atomicAdd(&g_cur[g_dst[i]], 1);
    g_srcp[p] = g_src[i];
}

// ---------------- tf32 tensor-core GEMM, double-buffered smem --------------
// C0 = A[N,M] @ W0[M,Kc], C1 = A @ W1 (blockIdx.y selects). 128x128 tile,
// 256 threads (8 warps as 2m x 4n, warp tile 64x32), K-chunk 32.
// Per chunk: issue global loads -> compute buf p -> store regs buf 1-p -> sync.
__device__ __forceinline__ unsigned f2tf32(float x) {
    unsigned r;
    asm("cvt.rna.tf32.f32 %0, %1;" : "=r"(r) : "f"(x));
    return r;
}
__device__ __forceinline__ void mma_tf32(float* c, unsigned a0, unsigned a1,
                                         unsigned a2, unsigned a3,
                                         unsigned b0, unsigned b1) {
    asm volatile(
        "mma.sync.aligned.m16n8k8.row.col.f32.tf32.tf32.f32 "
        "{%0,%1,%2,%3}, {%4,%5,%6,%7}, {%8,%9}, {%0,%1,%2,%3};"
        : "+f"(c[0]), "+f"(c[1]), "+f"(c[2]), "+f"(c[3])
        : "r"(a0), "r"(a1), "r"(a2), "r"(a3), "r"(b0), "r"(b1));
}

#define GEMM_SMEM (2 * 2 * 32 * 132 * 4)

__global__ __launch_bounds__(256, 1)
void k_gemm(const float* __restrict__ A,
            const float* __restrict__ W0, const float* __restrict__ W1,
            float* __restrict__ C0, float* __restrict__ C1,
            int N, int M, int Kc) {
    extern __shared__ unsigned sh[];
    unsigned (*As)[32][132] = (unsigned (*)[32][132])sh;             // [2][32][132]
    unsigned (*Bs)[32][132] = (unsigned (*)[32][132])(sh + 2 * 32 * 132);
    const int t = threadIdx.x;
    const int lane = t & 31, warp = t >> 5;
    const int wm = (warp >> 2) << 6;   // 0 / 64
    const int wn = (warp & 3) << 5;    // 0..96
    const int row0 = blockIdx.x * 128;
    int col0 = blockIdx.y * 128;
    const float* W = W0;
    float* C = C0;
    if (col0 >= Kc) { col0 -= Kc; W = W1; C = C1; }

    float acc[4][4][4];
#pragma unroll
    for (int mt = 0; mt < 4; mt++)
#pragma unroll
        for (int nt = 0; nt < 4; nt++)
#pragma unroll
            for (int j = 0; j < 4; j++) acc[mt][nt][j] = 0.f;

    const int arow = t >> 1;             // 0..127
    const int akq  = (t & 1) * 16;       // 0 / 16 float offset within chunk
    const int brow = t >> 3;             // 0..31 (k)
    const int bql  = (t & 7) * 4;        // n offset, +32 per q
    const bool aok = (row0 + arow) < N;

    float4 aR[4], bR[4];
    {   // chunk 0: load + store to buffer 0
        const float* ap = A + (size_t)(row0 + arow) * M + akq;
#pragma unroll
        for (int q = 0; q < 4; q++)
            aR[q] = aok ? *(const float4*)(ap + q * 4)
                        : make_float4(0.f, 0.f, 0.f, 0.f);
        const float* bp = W + (size_t)brow * Kc + col0 + bql;
#pragma unroll
        for (int q = 0; q < 4; q++)
            bR[q] = *(const float4*)(bp + q * 32);
#pragma unroll
        for (int q = 0; q < 4; q++) {
            int k = akq + q * 4;
            As[0][k + 0][arow] = f2tf32(aR[q].x);
            As[0][k + 1][arow] = f2tf32(aR[q].y);
            As[0][k + 2][arow] = f2tf32(aR[q].z);
            As[0][k + 3][arow] = f2tf32(aR[q].w);
        }
#pragma unroll
        for (int q = 0; q < 4; q++) {
            int nb = bql + q * 32;
            Bs[0][brow][nb + 0] = f2tf32(bR[q].x);
            Bs[0][brow][nb + 1] = f2tf32(bR[q].y);
            Bs[0][brow][nb + 2] = f2tf32(bR[q].z);
            Bs[0][brow][nb + 3] = f2tf32(bR[q].w);
        }
    }
    __syncthreads();

    const int nchunk = M >> 5;
    const int r = lane >> 2, c = lane & 3;
    for (int ch = 0; ch < nchunk; ch++) {
        int p = ch & 1;
        bool more = (ch + 1 < nchunk);
        if (more) {                      // issue next chunk's global loads now
            int k0 = (ch + 1) << 5;
            const float* ap = A + (size_t)(row0 + arow) * M + k0 + akq;
#pragma unroll
            for (int q = 0; q < 4; q++)
                aR[q] = aok ? *(const float4*)(ap + q * 4)
                            : make_float4(0.f, 0.f, 0.f, 0.f);
            const float* bp = W + (size_t)(k0 + brow) * Kc + col0 + bql;
#pragma unroll
            for (int q = 0; q < 4; q++)
                bR[q] = *(const float4*)(bp + q * 32);
        }
        // compute from buffer p (hides the global load latency above)
#pragma unroll
        for (int ks = 0; ks < 4; ks++) {
            int k = ks * 8;
            unsigned a[4][4], b[4][2];
#pragma unroll
            for (int mt = 0; mt < 4; mt++) {
                int mb = wm + mt * 16 + r;
                a[mt][0] = As[p][k + c][mb];
                a[mt][1] = As[p][k + c][mb + 8];
                a[mt][2] = As[p][k + c + 4][mb];
                a[mt][3] = As[p][k + c + 4][mb + 8];
            }
#pragma unroll
            for (int nt = 0; nt < 4; nt++) {
                int nb = wn + nt * 8 + r;
                b[nt][0] = Bs[p][k + c][nb];
                b[nt][1] = Bs[p][k + c + 4][nb];
            }
#pragma unroll
            for (int mt = 0; mt < 4; mt++)
#pragma unroll
                for (int nt = 0; nt < 4; nt++)
                    mma_tf32(acc[mt][nt], a[mt][0], a[mt][1], a[mt][2],
                             a[mt][3], b[nt][0], b[nt][1]);
        }
        if (more) {                      // store next chunk to other buffer
            int np = p ^ 1;
#pragma unroll
            for (int q = 0; q < 4; q++) {
                int k = akq + q * 4;
                As[np][k + 0][arow] = f2tf32(aR[q].x);
                As[np][k + 1][arow] = f2tf32(aR[q].y);
                As[np][k + 2][arow] = f2tf32(aR[q].z);
                As[np][k + 3][arow] = f2tf32(aR[q].w);
            }
#pragma unroll
            for (int q = 0; q < 4; q++) {
                int nb = bql + q * 32;
                Bs[np][brow][nb + 0] = f2tf32(bR[q].x);
                Bs[np][brow][nb + 1] = f2tf32(bR[q].y);
                Bs[np][brow][nb + 2] = f2tf32(bR[q].z);
                Bs[np][brow][nb + 3] = f2tf32(bR[q].w);
            }
            __syncthreads();
        }
    }
    // epilogue
    const int c2 = (lane & 3) * 2;
#pragma unroll
    for (int mt = 0; mt < 4; mt++) {
#pragma unroll
        for (int half = 0; half < 2; half++) {
            int row = row0 + wm + mt * 16 + r + half * 8;
            if (row < N) {
#pragma unroll
                for (int nt = 0; nt < 4; nt++) {
                    float2 v = half
                        ? make_float2(acc[mt][nt][2], acc[mt][nt][3])
                        : make_float2(acc[mt][nt][0], acc[mt][nt][1]);
                    *(float2*)(C + (size_t)row * Kc + col0 + wn + nt * 8 + c2) = v;
                }
            }
        }
    }
}

// ---------------- fused GATv2 edge pass: logit + online softmax + agg ------
// One warp per dst node. Lane l owns dims [4l..4l+3] (head hA=l>>3) in float4
// A and dims [128+4l..128+4l+3] (head hA+4) in float4 B. Next edge's xl row
// is prefetched before the shfl/exp chain (software pipeline).
// MODE 0: bias+ELU, write 256-wide h. MODE 1: head-mean + bias, 32-wide out.
template<int MODE>
__global__ void k_fused(const float* __restrict__ xl, const float* __restrict__ xr,
                        const float* __restrict__ att, const float* __restrict__ bias,
                        float* __restrict__ out) {
    int n = (blockIdx.x * blockDim.x + threadIdx.x) >> 5;
    int lane = threadIdx.x & 31;
    if (n >= NN) return;
    int beg = g_off[n], end = g_off[n + 1];

    // per-dst target transform + attention vector slices (register resident)
    const float4* xrp = (const float4*)(xr + (size_t)n * D1);
    float4 r0 = xrp[lane], r1 = xrp[32 + lane];
    float4 atA = *(const float4*)(att + 4 * lane);
    float4 atB = *(const float4*)(att + 128 + 4 * lane);

    float mA = -1e30f, mB = -1e30f, sA = 0.f, sB = 0.f;
    float4 acc0 = make_float4(0.f, 0.f, 0.f, 0.f);
    float4 acc1 = make_float4(0.f, 0.f, 0.f, 0.f);

    // prefetch first edge (every node has a self-loop, so beg < end)
    int s = __ldg(&g_srcp[beg]);
    const float4* xs = (const float4*)(xl + (size_t)s * D1);
    float4 v0 = xs[lane], v1 = xs[32 + lane];

    for (int i = beg; i < end; i++) {
        float4 cv0 = v0, cv1 = v1;
        if (i + 1 < end) {               // issue next edge's loads early
            int sn = __ldg(&g_srcp[i + 1]);
            const float4* xn = (const float4*)(xl + (size_t)sn * D1);
            v0 = xn[lane];
            v1 = xn[32 + lane];
        }
        // GATv2 logit contribution: leakyrelu(xl+xr) . att
        float z, cA, cB;
        z = cv0.x + r0.x; z = z > 0.f ? z : 0.2f * z; cA  = z * atA.x;
        z = cv0.y + r0.y; z = z > 0.f ? z : 0.2f * z; cA += z * atA.y;
        z = cv0.z + r0.z; z = z > 0.f ? z : 0.2f * z; cA += z * atA.z;
        z = cv0.w + r0.w; z = z > 0.f ? z : 0.2f * z; cA += z * atA.w;
        z = cv1.x + r1.x; z = z > 0.f ? z : 0.2f * z; cB  = z * atB.x;
        z = cv1.y + r1.y; z = z > 0.f ? z : 0.2f * z; cB += z * atB.y;
        z = cv1.z + r1.z; z = z > 0.f ? z : 0.2f * z; cB += z * atB.z;
        z = cv1.w + r1.w; z = z > 0.f ? z : 0.2f * z; cB += z * atB.w;
        // reduce within each 8-lane head group
#pragma unroll
        for (int off = 1; off < 8; off <<= 1) {
            cA += __shfl_xor_sync(0xffffffffu, cA, off);
            cB += __shfl_xor_sync(0xffffffffu, cB, off);
        }
        // online softmax update (head A)
        float mAn = fmaxf(mA, cA);
        float scA = __expf(mA - mAn);
        float pA  = __expf(cA - mAn);
        sA = sA * scA + pA;
        acc0.x = acc0.x * scA + pA * cv0.x;
        acc0.y = acc0.y * scA + pA * cv0.y;
        acc0.z = acc0.z * scA + pA * cv0.z;
        acc0.w = acc0.w * scA + pA * cv0.w;
        mA = mAn;
        // head B
        float mBn = fmaxf(mB, cB);
        float scB = __expf(mB - mBn);
        float pB  = __expf(cB - mBn);
        sB = sB * scB + pB;
        acc1.x = acc1.x * scB + pB * cv1.x;
        acc1.y = acc1.y * scB + pB * cv1.y;
        acc1.z = acc1.z * scB + pB * cv1.z;
        acc1.w = acc1.w * scB + pB * cv1.w;
        mB = mBn;
    }
    float iA = 1.f / (sA + 1e-16f);
    float iB = 1.f / (sB + 1e-16f);
    acc0.x *= iA; acc0.y *= iA; acc0.z *= iA; acc0.w *= iA;
    acc1.x *= iB; acc1.y *= iB; acc1.z *= iB; acc1.w *= iB;

    if (MODE == 1) {
        // head-mean: both float4s map to output cols 4*(lane&7)..+3; sum
        // heads across lanes {l, l^8, l^16, l^24}
        float4 tv = make_float4(acc0.x + acc1.x, acc0.y + acc1.y,
                                acc0.z + acc1.z, acc0.w + acc1.w);
#pragma unroll
        for (int off = 8; off <= 16; off <<= 1) {
            tv.x += __shfl_xor_sync(0xffffffffu, tv.x, off);
            tv.y += __shfl_xor_sync(0xffffffffu, tv.y, off);
            tv.z += __shfl_xor_sync(0xffffffffu, tv.z, off);
            tv.w += __shfl_xor_sync(0xffffffffu, tv.w, off);
        }
        if (lane < 8) {
            float4 bb = *(const float4*)(bias + lane * 4);
            float4 r = make_float4(tv.x * 0.125f + bb.x, tv.y * 0.125f + bb.y,
                                   tv.z * 0.125f + bb.z, tv.w * 0.125f + bb.w);
            *(float4*)(out + (size_t)n * 32 + lane * 4) = r;
        }
    } else {
        // fused bias + ELU for layer 1 hidden state
        float4 b0 = *(const float4*)(bias + lane * 4);
        float4 b1 = *(const float4*)(bias + 128 + lane * 4);
        float4 w0, w1;
        float v;
        v = acc0.x + b0.x; w0.x = v > 0.f ? v : expm1f(v);
        v = acc0.y + b0.y; w0.y = v > 0.f ? v : expm1f(v);
        v = acc0.z + b0.z; w0.z = v > 0.f ? v : expm1f(v);
        v = acc0.w + b0.w; w0.w = v > 0.f ? v : expm1f(v);
        v = acc1.x + b1.x; w1.x = v > 0.f ? v : expm1f(v);
        v = acc1.y + b1.y; w1.y = v > 0.f ? v : expm1f(v);
        v = acc1.z + b1.z; w1.z = v > 0.f ? v : expm1f(v);
        v = acc1.w + b1.w; w1.w = v > 0.f ? v : expm1f(v);
        float4* op = (float4*)(out + (size_t)n * D1);
        op[lane] = w0;
        op[32 + lane] = w1;
    }
}

// ---------------- launch ---------------------------------------------------
extern "C" void kernel_launch(void* const* d_in, const int* in_sizes, int n_in,
                              void* d_out, int out_size) {
    const float* x    = (const float*)d_in[0];
    const void*  ei   = d_in[1];
    const float* Wl1  = (const float*)d_in[2];
    const float* Wr1  = (const float*)d_in[3];
    const float* att1 = (const float*)d_in[4];
    const float* b1   = (const float*)d_in[5];
    const float* Wl2  = (const float*)d_in[6];
    const float* Wr2  = (const float*)d_in[7];
    const float* att2 = (const float*)d_in[8];
    const float* b2   = (const float*)d_in[9];

    float *pxl, *pxr, *ph;
    cudaGetSymbolAddress((void**)&pxl, g_xl);
    cudaGetSymbolAddress((void**)&pxr, g_xr);
    cudaGetSymbolAddress((void**)&ph,  g_h);

    cudaFuncSetAttribute(k_gemm, cudaFuncAttributeMaxDynamicSharedMemorySize,
                         GEMM_SMEM);

    // graph prep (4 launches)
    k_detect_zero<<<(NN + 255) / 256, 256>>>((const unsigned*)ei);
    k_build_count<<<(NE + 255) / 256, 256>>>(ei);
    k_scan<<<1, 1024>>>();
    k_scatter<<<(NE + 255) / 256, 256>>>();

    dim3 gg((NN + 127) / 128, 2 * D1 / 128);   // both Wl and Wr outputs
    const int ab = (NN * 32 + 255) / 256;      // warp per dst

    // layer 1
    k_gemm<<<gg, 256, GEMM_SMEM>>>(x, Wl1, Wr1, pxl, pxr, NN, 128, D1);
    k_fused<0><<<ab, 256>>>(pxl, pxr, att1, b1, ph);

    // layer 2
    k_gemm<<<gg, 256, GEMM_SMEM>>>(ph, Wl2, Wr2, pxl, pxr, NN, 256, D1);
    k_fused<1><<<ab, 256>>>(pxl, pxr, att2, b2, (float*)d_out);
}

// round 6
// speedup vs baseline: 2.3596x; 1.0279x over previous
#include <cuda_runtime.h>
#include <cstdint>
#include <math.h>

#define NN 50000
#define EE 800000
#define NE 850000      // EE + NN self loops
#define D1 256         // H*DH = H*DOUT paths both 256 wide

// ---------------- scratch (device globals; no allocation allowed) ----------
__device__ int   g_is64;
__device__ int   g_src[NE];     // edge order
__device__ int   g_dst[NE];
__device__ int   g_srcp[NE];    // CSR (dst-grouped) order
__device__ int   g_deg[NN];
__device__ int   g_off[NN + 1];
__device__ int   g_cur[NN];
__device__ float g_xl[(size_t)NN * D1];
__device__ float g_xr[(size_t)NN * D1];
__device__ float g_h [(size_t)NN * D1];

// ---------------- detect dtype (block 0) + zero degree array ---------------
__global__ void k_detect_zero(const unsigned* __restrict__ p) {
    int i = blockIdx.x * blockDim.x + threadIdx.x;
    if (i < NN) g_deg[i] = 0;
    if (blockIdx.x == 0) {
        __shared__ unsigned acc;
        if (threadIdx.x == 0) acc = 0u;
        __syncthreads();
        if (threadIdx.x < 128) {
            unsigned v = p[threadIdx.x * 2 + 1];
            if (v) atomicOr(&acc, 1u);
        }
        __syncthreads();
        if (threadIdx.x == 0) g_is64 = (acc == 0u) ? 1 : 0;
    }
}

// ---------------- build src/dst with self loops + degree count -------------
__global__ void k_build_count(const void* __restrict__ ei) {
    int i = blockIdx.x * blockDim.x + threadIdx.x;
    if (i >= NE) return;
    int s, d;
    if (i < EE) {
        if (g_is64) {
            const long long* p = (const long long*)ei;
            s = (int)p[i];
            d = (int)p[EE + i];
        } else {
            const int* p = (const int*)ei;
            s = p[i];
            d = p[EE + i];
        }
    } else {
        s = d = i - EE;
    }
    g_src[i] = s;
    g_dst[i] = d;
    atomicAdd(&g_deg[d], 1);
}

// single-block exclusive scan over 50000 counts
__global__ void k_scan() {
    const int T = 1024, CH = 49;     // 1024*49 = 50176 >= NN
    __shared__ int sm[T];
    int t = threadIdx.x;
    int beg = t * CH, end = min(beg + CH, NN);
    int s = 0;
    for (int i = beg; i < end; i++) s += g_deg[i];
    sm[t] = s;
    __syncthreads();
    for (int off = 1; off < T; off <<= 1) {
        int v = (t >= off) ? sm[t - off] : 0;
        __syncthreads();
        sm[t] += v;
        __syncthreads();
    }
    int run = sm[t] - s;            // exclusive prefix
    for (int i = beg; i < end; i++) {
        g_off[i] = run;
        g_cur[i] = run;
        run += g_deg[i];
    }
    if (t == T - 1) g_off[NN] = sm[T - 1];
}

__global__ void k_scatter() {
    int i = blockIdx.x * blockDim.x + threadIdx.x;
    if (i >= NE) return;
    int p = atomicAdd(&g_cur[g_dst[i]], 1);
    g_srcp[p] = g_src[i];
}

// ---------------- tf32 tensor-core GEMM, double-buffered, 2 CTA/SM ---------
// C0 = A[N,M] @ W0[M,Kc], C1 = A @ W1 (blockIdx.y selects). 128x128 tile,
// 256 threads (8 warps as 2m x 4n, warp tile 64x32), K-chunk 16.
// smem = 33.8 KB -> two CTAs co-resident per SM for latency hiding.
__device__ __forceinline__ unsigned f2tf32(float x) {
    unsigned r;
    asm("cvt.rna.tf32.f32 %0, %1;" : "=r"(r) : "f"(x));
    return r;
}
__device__ __forceinline__ void mma_tf32(float* c, unsigned a0, unsigned a1,
                                         unsigned a2, unsigned a3,
                                         unsigned b0, unsigned b1) {
    asm volatile(
        "mma.sync.aligned.m16n8k8.row.col.f32.tf32.tf32.f32 "
        "{%0,%1,%2,%3}, {%4,%5,%6,%7}, {%8,%9}, {%0,%1,%2,%3};"
        : "+f"(c[0]), "+f"(c[1]), "+f"(c[2]), "+f"(c[3])
        : "r"(a0), "r"(a1), "r"(a2), "r"(a3), "r"(b0), "r"(b1));
}

__global__ __launch_bounds__(256, 2)
void k_gemm(const float* __restrict__ A,
            const float* __restrict__ W0, const float* __restrict__ W1,
            float* __restrict__ C0, float* __restrict__ C1,
            int N, int M, int Kc) {
    __shared__ unsigned As[2][16][132];   // [buf][k][m] padded
    __shared__ unsigned Bs[2][16][132];   // [buf][k][n]
    const int t = threadIdx.x;
    const int lane = t & 31, warp = t >> 5;
    const int wm = (warp >> 2) << 6;   // 0 / 64
    const int wn = (warp & 3) << 5;    // 0..96
    const int row0 = blockIdx.x * 128;
    int col0 = blockIdx.y * 128;
    const float* W = W0;
    float* C = C0;
    if (col0 >= Kc) { col0 -= Kc; W = W1; C = C1; }

    float acc[4][4][4];
#pragma unroll
    for (int mt = 0; mt < 4; mt++)
#pragma unroll
        for (int nt = 0; nt < 4; nt++)
#pragma unroll
            for (int j = 0; j < 4; j++) acc[mt][nt][j] = 0.f;

    const int arow = t >> 1;             // 0..127
    const int ak   = (t & 1) * 8;        // 0 / 8 float offset in chunk
    const int brow = t >> 4;             // 0..15 (k)
    const int bcol = (t & 15) * 4;       // n offset; second float4 at +64
    const bool aok = (row0 + arow) < N;

    float4 aR[2], bR[2];
    {   // chunk 0: load + store to buffer 0
        const float* ap = A + (size_t)(row0 + arow) * M + ak;
#pragma unroll
        for (int q = 0; q < 2; q++)
            aR[q] = aok ? *(const float4*)(ap + q * 4)
                        : make_float4(0.f, 0.f, 0.f, 0.f);
        const float* bp = W + (size_t)brow * Kc + col0 + bcol;
#pragma unroll
        for (int q = 0; q < 2; q++)
            bR[q] = *(const float4*)(bp + q * 64);
#pragma unroll
        for (int q = 0; q < 2; q++) {
            int k = ak + q * 4;
            As[0][k + 0][arow] = f2tf32(aR[q].x);
            As[0][k + 1][arow] = f2tf32(aR[q].y);
            As[0][k + 2][arow] = f2tf32(aR[q].z);
            As[0][k + 3][arow] = f2tf32(aR[q].w);
        }
#pragma unroll
        for (int q = 0; q < 2; q++) {
            int nb = bcol + q * 64;
            Bs[0][brow][nb + 0] = f2tf32(bR[q].x);
            Bs[0][brow][nb + 1] = f2tf32(bR[q].y);
            Bs[0][brow][nb + 2] = f2tf32(bR[q].z);
            Bs[0][brow][nb + 3] = f2tf32(bR[q].w);
        }
    }
    __syncthreads();

    const int nchunk = M >> 4;
    const int r = lane >> 2, c = lane & 3;
    for (int ch = 0; ch < nchunk; ch++) {
        int p = ch & 1;
        bool more = (ch + 1 < nchunk);
        if (more) {                      // issue next chunk's global loads now
            int k0 = (ch + 1) << 4;
            const float* ap = A + (size_t)(row0 + arow) * M + k0 + ak;
#pragma unroll
            for (int q = 0; q < 2; q++)
                aR[q] = aok ? *(const float4*)(ap + q * 4)
                            : make_float4(0.f, 0.f, 0.f, 0.f);
            const float* bp = W + (size_t)(k0 + brow) * Kc + col0 + bcol;
#pragma unroll
            for (int q = 0; q < 2; q++)
                bR[q] = *(const float4*)(bp + q * 64);
        }
        // compute from buffer p (hides the global load latency above)
#pragma unroll
        for (int ks = 0; ks < 2; ks++) {
            int k = ks * 8;
            unsigned a[4][4], b[4][2];
#pragma unroll
            for (int mt = 0; mt < 4; mt++) {
                int mb = wm + mt * 16 + r;
                a[mt][0] = As[p][k + c][mb];
                a[mt][1] = As[p][k + c][mb + 8];
                a[mt][2] = As[p][k + c + 4][mb];
                a[mt][3] = As[p][k + c + 4][mb + 8];
            }
#pragma unroll
            for (int nt = 0; nt < 4; nt++) {
                int nb = wn + nt * 8 + r;
                b[nt][0] = Bs[p][k + c][nb];
                b[nt][1] = Bs[p][k + c + 4][nb];
            }
#pragma unroll
            for (int mt = 0; mt < 4; mt++)
#pragma unroll
                for (int nt = 0; nt < 4; nt++)
                    mma_tf32(acc[mt][nt], a[mt][0], a[mt][1], a[mt][2],
                             a[mt][3], b[nt][0], b[nt][1]);
        }
        if (more) {                      // store next chunk to other buffer
            int np = p ^ 1;
#pragma unroll
            for (int q = 0; q < 2; q++) {
                int k = ak + q * 4;
                As[np][k + 0][arow] = f2tf32(aR[q].x);
                As[np][k + 1][arow] = f2tf32(aR[q].y);
                As[np][k + 2][arow] = f2tf32(aR[q].z);
                As[np][k + 3][arow] = f2tf32(aR[q].w);
            }
#pragma unroll
            for (int q = 0; q < 2; q++) {
                int nb = bcol + q * 64;
                Bs[np][brow][nb + 0] = f2tf32(bR[q].x);
                Bs[np][brow][nb + 1] = f2tf32(bR[q].y);
                Bs[np][brow][nb + 2] = f2tf32(bR[q].z);
                Bs[np][brow][nb + 3] = f2tf32(bR[q].w);
            }
            __syncthreads();
        }
    }
    // epilogue
    const int c2 = (lane & 3) * 2;
#pragma unroll
    for (int mt = 0; mt < 4; mt++) {
#pragma unroll
        for (int half = 0; half < 2; half++) {
            int row = row0 + wm + mt * 16 + r + half * 8;
            if (row < N) {
#pragma unroll
                for (int nt = 0; nt < 4; nt++) {
                    float2 v = half
                        ? make_float2(acc[mt][nt][2], acc[mt][nt][3])
                        : make_float2(acc[mt][nt][0], acc[mt][nt][1]);
                    *(float2*)(C + (size_t)row * Kc + col0 + wn + nt * 8 + c2) = v;
                }
            }
        }
    }
}

// ---------------- fused GATv2 edge pass: logit + online softmax + agg ------
// One warp per dst node. Lane l owns dims [4l..4l+3] (head hA=l>>3) in float4
// A and dims [128+4l..128+4l+3] (head hA+4) in float4 B. Next edge's xl row
// is prefetched before the shfl/exp chain (software pipeline).
// MODE 0: bias+ELU, write 256-wide h. MODE 1: head-mean + bias, 32-wide out.
template<int MODE>
__global__ void k_fused(const float* __restrict__ xl, const float* __restrict__ xr,
                        const float* __restrict__ att, const float* __restrict__ bias,
                        float* __restrict__ out) {
    int n = (blockIdx.x * blockDim.x + threadIdx.x) >> 5;
    int lane = threadIdx.x & 31;
    if (n >= NN) return;
    int beg = g_off[n], end = g_off[n + 1];

    // per-dst target transform + attention vector slices (register resident)
    const float4* xrp = (const float4*)(xr + (size_t)n * D1);
    float4 r0 = xrp[lane], r1 = xrp[32 + lane];
    float4 atA = *(const float4*)(att + 4 * lane);
    float4 atB = *(const float4*)(att + 128 + 4 * lane);

    float mA = -1e30f, mB = -1e30f, sA = 0.f, sB = 0.f;
    float4 acc0 = make_float4(0.f, 0.f, 0.f, 0.f);
    float4 acc1 = make_float4(0.f, 0.f, 0.f, 0.f);

    // prefetch first edge (every node has a self-loop, so beg < end)
    int s = __ldg(&g_srcp[beg]);
    const float4* xs = (const float4*)(xl + (size_t)s * D1);
    float4 v0 = xs[lane], v1 = xs[32 + lane];

    for (int i = beg; i < end; i++) {
        float4 cv0 = v0, cv1 = v1;
        if (i + 1 < end) {               // issue next edge's loads early
            int sn = __ldg(&g_srcp[i + 1]);
            const float4* xn = (const float4*)(xl + (size_t)sn * D1);
            v0 = xn[lane];
            v1 = xn[32 + lane];
        }
        // GATv2 logit contribution: leakyrelu(xl+xr) . att
        float z, cA, cB;
        z = cv0.x + r0.x; z = z > 0.f ? z : 0.2f * z; cA  = z * atA.x;
        z = cv0.y + r0.y; z = z > 0.f ? z : 0.2f * z; cA += z * atA.y;
        z = cv0.z + r0.z; z = z > 0.f ? z : 0.2f * z; cA += z * atA.z;
        z = cv0.w + r0.w; z = z > 0.f ? z : 0.2f * z; cA += z * atA.w;
        z = cv1.x + r1.x; z = z > 0.f ? z : 0.2f * z; cB  = z * atB.x;
        z = cv1.y + r1.y; z = z > 0.f ? z : 0.2f * z; cB += z * atB.y;
        z = cv1.z + r1.z; z = z > 0.f ? z : 0.2f * z; cB += z * atB.z;
        z = cv1.w + r1.w; z = z > 0.f ? z : 0.2f * z; cB += z * atB.w;
        // reduce within each 8-lane head group
#pragma unroll
        for (int off = 1; off < 8; off <<= 1) {
            cA += __shfl_xor_sync(0xffffffffu, cA, off);
            cB += __shfl_xor_sync(0xffffffffu, cB, off);
        }
        // online softmax update (head A)
        float mAn = fmaxf(mA, cA);
        float scA = __expf(mA - mAn);
        float pA  = __expf(cA - mAn);
        sA = sA * scA + pA;
        acc0.x = acc0.x * scA + pA * cv0.x;
        acc0.y = acc0.y * scA + pA * cv0.y;
        acc0.z = acc0.z * scA + pA * cv0.z;
        acc0.w = acc0.w * scA + pA * cv0.w;
        mA = mAn;
        // head B
        float mBn = fmaxf(mB, cB);
        float scB = __expf(mB - mBn);
        float pB  = __expf(cB - mBn);
        sB = sB * scB + pB;
        acc1.x = acc1.x * scB + pB * cv1.x;
        acc1.y = acc1.y * scB + pB * cv1.y;
        acc1.z = acc1.z * scB + pB * cv1.z;
        acc1.w = acc1.w * scB + pB * cv1.w;
        mB = mBn;
    }
    float iA = 1.f / (sA + 1e-16f);
    float iB = 1.f / (sB + 1e-16f);
    acc0.x *= iA; acc0.y *= iA; acc0.z *= iA; acc0.w *= iA;
    acc1.x *= iB; acc1.y *= iB; acc1.z *= iB; acc1.w *= iB;

    if (MODE == 1) {
        // head-mean: both float4s map to output cols 4*(lane&7)..+3; sum
        // heads across lanes {l, l^8, l^16, l^24}
        float4 tv = make_float4(acc0.x + acc1.x, acc0.y + acc1.y,
                                acc0.z + acc1.z, acc0.w + acc1.w);
#pragma unroll
        for (int off = 8; off <= 16; off <<= 1) {
            tv.x += __shfl_xor_sync(0xffffffffu, tv.x, off);
            tv.y += __shfl_xor_sync(0xffffffffu, tv.y, off);
            tv.z += __shfl_xor_sync(0xffffffffu, tv.z, off);
            tv.w += __shfl_xor_sync(0xffffffffu, tv.w, off);
        }
        if (lane < 8) {
            float4 bb = *(const float4*)(bias + lane * 4);
            float4 r = make_float4(tv.x * 0.125f + bb.x, tv.y * 0.125f + bb.y,
                                   tv.z * 0.125f + bb.z, tv.w * 0.125f + bb.w);
            *(float4*)(out + (size_t)n * 32 + lane * 4) = r;
        }
    } else {
        // fused bias + ELU for layer 1 hidden state
        float4 b0 = *(const float4*)(bias + lane * 4);
        float4 b1 = *(const float4*)(bias + 128 + lane * 4);
        float4 w0, w1;
        float v;
        v = acc0.x + b0.x; w0.x = v > 0.f ? v : expm1f(v);
        v = acc0.y + b0.y; w0.y = v > 0.f ? v : expm1f(v);
        v = acc0.z + b0.z; w0.z = v > 0.f ? v : expm1f(v);
        v = acc0.w + b0.w; w0.w = v > 0.f ? v : expm1f(v);
        v = acc1.x + b1.x; w1.x = v > 0.f ? v : expm1f(v);
        v = acc1.y + b1.y; w1.y = v > 0.f ? v : expm1f(v);
        v = acc1.z + b1.z; w1.z = v > 0.f ? v : expm1f(v);
        v = acc1.w + b1.w; w1.w = v > 0.f ? v : expm1f(v);
        float4* op = (float4*)(out + (size_t)n * D1);
        op[lane] = w0;
        op[32 + lane] = w1;
    }
}

// ---------------- launch ---------------------------------------------------
extern "C" void kernel_launch(void* const* d_in, const int* in_sizes, int n_in,
                              void* d_out, int out_size) {
    const float* x    = (const float*)d_in[0];
    const void*  ei   = d_in[1];
    const float* Wl1  = (const float*)d_in[2];
    const float* Wr1  = (const float*)d_in[3];
    const float* att1 = (const float*)d_in[4];
    const float* b1   = (const float*)d_in[5];
    const float* Wl2  = (const float*)d_in[6];
    const float* Wr2  = (const float*)d_in[7];
    const float* att2 = (const float*)d_in[8];
    const float* b2   = (const float*)d_in[9];

    float *pxl, *pxr, *ph;
    cudaGetSymbolAddress((void**)&pxl, g_xl);
    cudaGetSymbolAddress((void**)&pxr, g_xr);
    cudaGetSymbolAddress((void**)&ph,  g_h);

    // graph prep (4 launches)
    k_detect_zero<<<(NN + 255) / 256, 256>>>((const unsigned*)ei);
    k_build_count<<<(NE + 255) / 256, 256>>>(ei);
    k_scan<<<1, 1024>>>();
    k_scatter<<<(NE + 255) / 256, 256>>>();

    dim3 gg((NN + 127) / 128, 2 * D1 / 128);   // both Wl and Wr outputs
    const int ab = (NN * 32 + 255) / 256;      // warp per dst

    // layer 1
    k_gemm<<<gg, 256>>>(x, Wl1, Wr1, pxl, pxr, NN, 128, D1);
    k_fused<0><<<ab, 256>>>(pxl, pxr, att1, b1, ph);

    // layer 2
    k_gemm<<<gg, 256>>>(ph, Wl2, Wr2, pxl, pxr, NN, 256, D1);
    k_fused<1><<<ab, 256>>>(pxl, pxr, att2, b2, (float*)d_out);
}

// round 7
// speedup vs baseline: 2.3624x; 1.0012x over previous
#include <cuda_runtime.h>
#include <cstdint>
#include <math.h>

#define NN 50000
#define EE 800000
#define NE 850000      // EE + NN self loops
#define D1 256         // H*DH = H*DOUT paths both 256 wide

// ---------------- scratch (device globals; no allocation allowed) ----------
__device__ int   g_is64;
__device__ int   g_src[NE];     // edge order
__device__ int   g_dst[NE];
__device__ int   g_srcp[NE];    // CSR (dst-grouped) order
__device__ int   g_deg[NN];
__device__ int   g_off[NN + 1];
__device__ int   g_cur[NN];
__device__ float g_xl[(size_t)NN * D1];
__device__ float g_xr[(size_t)NN * D1];
__device__ float g_h [(size_t)NN * D1];

// ---------------- detect dtype (block 0) + zero degree array ---------------
__global__ void k_detect_zero(const unsigned* __restrict__ p) {
    int i = blockIdx.x * blockDim.x + threadIdx.x;
    if (i < NN) g_deg[i] = 0;
    if (blockIdx.x == 0) {
        __shared__ unsigned acc;
        if (threadIdx.x == 0) acc = 0u;
        __syncthreads();
        if (threadIdx.x < 128) {
            unsigned v = p[threadIdx.x * 2 + 1];
            if (v) atomicOr(&acc, 1u);
        }
        __syncthreads();
        if (threadIdx.x == 0) g_is64 = (acc == 0u) ? 1 : 0;
    }
}

// ---------------- build src/dst with self loops + degree count -------------
__global__ void k_build_count(const void* __restrict__ ei) {
    int i = blockIdx.x * blockDim.x + threadIdx.x;
    if (i >= NE) return;
    int s, d;
    if (i < EE) {
        if (g_is64) {
            const long long* p = (const long long*)ei;
            s = (int)p[i];
            d = (int)p[EE + i];
        } else {
            const int* p = (const int*)ei;
            s = p[i];
            d = p[EE + i];
        }
    } else {
        s = d = i - EE;
    }
    g_src[i] = s;
    g_dst[i] = d;
    atomicAdd(&g_deg[d], 1);
}

// single-block exclusive scan over 50000 counts
__global__ void k_scan() {
    const int T = 1024, CH = 49;     // 1024*49 = 50176 >= NN
    __shared__ int sm[T];
    int t = threadIdx.x;
    int beg = t * CH, end = min(beg + CH, NN);
    int s = 0;
    for (int i = beg; i < end; i++) s += g_deg[i];
    sm[t] = s;
    __syncthreads();
    for (int off = 1; off < T; off <<= 1) {
        int v = (t >= off) ? sm[t - off] : 0;
        __syncthreads();
        sm[t] += v;
        __syncthreads();
    }
    int run = sm[t] - s;            // exclusive prefix
    for (int i = beg; i < end; i++) {
        g_off[i] = run;
        g_cur[i] = run;
        run += g_deg[i];
    }
    if (t == T - 1) g_off[NN] = sm[T - 1];
}

__global__ void k_scatter() {
    int i = blockIdx.x * blockDim.x + threadIdx.x;
    if (i >= NE) return;
    int p = atomicAdd(&g_cur[g_dst[i]], 1);
    g_srcp[p] = g_src[i];
}

// ---------------- tf32 tensor-core GEMM, double-buffered, 2 CTA/SM ---------
// C0 = A[N,M] @ W0[M,Kc], C1 = A @ W1 (blockIdx.y selects). 128x128 tile,
// 256 threads (8 warps as 2m x 4n, warp tile 64x32), K-chunk 16.
// smem = 33.8 KB -> two CTAs co-resident per SM for latency hiding.
__device__ __forceinline__ unsigned f2tf32(float x) {
    unsigned r;
    asm("cvt.rna.tf32.f32 %0, %1;" : "=r"(r) : "f"(x));
    return r;
}
__device__ __forceinline__ void mma_tf32(float* c, unsigned a0, unsigned a1,
                                         unsigned a2, unsigned a3,
                                         unsigned b0, unsigned b1) {
    asm volatile(
        "mma.sync.aligned.m16n8k8.row.col.f32.tf32.tf32.f32 "
        "{%0,%1,%2,%3}, {%4,%5,%6,%7}, {%8,%9}, {%0,%1,%2,%3};"
        : "+f"(c[0]), "+f"(c[1]), "+f"(c[2]), "+f"(c[3])
        : "r"(a0), "r"(a1), "r"(a2), "r"(a3), "r"(b0), "r"(b1));
}

__global__ __launch_bounds__(256, 2)
void k_gemm(const float* __restrict__ A,
            const float* __restrict__ W0, const float* __restrict__ W1,
            float* __restrict__ C0, float* __restrict__ C1,
            int N, int M, int Kc) {
    __shared__ unsigned As[2][16][132];   // [buf][k][m] padded
    __shared__ unsigned Bs[2][16][132];   // [buf][k][n]
    const int t = threadIdx.x;
    const int lane = t & 31, warp = t >> 5;
    const int wm = (warp >> 2) << 6;   // 0 / 64
    const int wn = (warp & 3) << 5;    // 0..96
    const int row0 = blockIdx.x * 128;
    int col0 = blockIdx.y * 128;
    const float* W = W0;
    float* C = C0;
    if (col0 >= Kc) { col0 -= Kc; W = W1; C = C1; }

    float acc[4][4][4];
#pragma unroll
    for (int mt = 0; mt < 4; mt++)
#pragma unroll
        for (int nt = 0; nt < 4; nt++)
#pragma unroll
            for (int j = 0; j < 4; j++) acc[mt][nt][j] = 0.f;

    const int arow = t >> 1;             // 0..127
    const int ak   = (t & 1) * 8;        // 0 / 8 float offset in chunk
    const int brow = t >> 4;             // 0..15 (k)
    const int bcol = (t & 15) * 4;       // n offset; second float4 at +64
    const bool aok = (row0 + arow) < N;

    float4 aR[2], bR[2];
    {   // chunk 0: load + store to buffer 0
        const float* ap = A + (size_t)(row0 + arow) * M + ak;
#pragma unroll
        for (int q = 0; q < 2; q++)
            aR[q] = aok ? *(const float4*)(ap + q * 4)
                        : make_float4(0.f, 0.f, 0.f, 0.f);
        const float* bp = W + (size_t)brow * Kc + col0 + bcol;
#pragma unroll
        for (int q = 0; q < 2; q++)
            bR[q] = *(const float4*)(bp + q * 64);
#pragma unroll
        for (int q = 0; q < 2; q++) {
            int k = ak + q * 4;
            As[0][k + 0][arow] = f2tf32(aR[q].x);
            As[0][k + 1][arow] = f2tf32(aR[q].y);
            As[0][k + 2][arow] = f2tf32(aR[q].z);
            As[0][k + 3][arow] = f2tf32(aR[q].w);
        }
#pragma unroll
        for (int q = 0; q < 2; q++) {
            int nb = bcol + q * 64;
            Bs[0][brow][nb + 0] = f2tf32(bR[q].x);
            Bs[0][brow][nb + 1] = f2tf32(bR[q].y);
            Bs[0][brow][nb + 2] = f2tf32(bR[q].z);
            Bs[0][brow][nb + 3] = f2tf32(bR[q].w);
        }
    }
    __syncthreads();

    const int nchunk = M >> 4;
    const int r = lane >> 2, c = lane & 3;
    for (int ch = 0; ch < nchunk; ch++) {
        int p = ch & 1;
        bool more = (ch + 1 < nchunk);
        if (more) {                      // issue next chunk's global loads now
            int k0 = (ch + 1) << 4;
            const float* ap = A + (size_t)(row0 + arow) * M + k0 + ak;
#pragma unroll
            for (int q = 0; q < 2; q++)
                aR[q] = aok ? *(const float4*)(ap + q * 4)
                            : make_float4(0.f, 0.f, 0.f, 0.f);
            const float* bp = W + (size_t)(k0 + brow) * Kc + col0 + bcol;
#pragma unroll
            for (int q = 0; q < 2; q++)
                bR[q] = *(const float4*)(bp + q * 64);
        }
        // compute from buffer p (hides the global load latency above)
#pragma unroll
        for (int ks = 0; ks < 2; ks++) {
            int k = ks * 8;
            unsigned a[4][4], b[4][2];
#pragma unroll
            for (int mt = 0; mt < 4; mt++) {
                int mb = wm + mt * 16 + r;
                a[mt][0] = As[p][k + c][mb];
                a[mt][1] = As[p][k + c][mb + 8];
                a[mt][2] = As[p][k + c + 4][mb];
                a[mt][3] = As[p][k + c + 4][mb + 8];
            }
#pragma unroll
            for (int nt = 0; nt < 4; nt++) {
                int nb = wn + nt * 8 + r;
                b[nt][0] = Bs[p][k + c][nb];
                b[nt][1] = Bs[p][k + c + 4][nb];
            }
#pragma unroll
            for (int mt = 0; mt < 4; mt++)
#pragma unroll
                for (int nt = 0; nt < 4; nt++)
                    mma_tf32(acc[mt][nt], a[mt][0], a[mt][1], a[mt][2],
                             a[mt][3], b[nt][0], b[nt][1]);
        }
        if (more) {                      // store next chunk to other buffer
            int np = p ^ 1;
#pragma unroll
            for (int q = 0; q < 2; q++) {
                int k = ak + q * 4;
                As[np][k + 0][arow] = f2tf32(aR[q].x);
                As[np][k + 1][arow] = f2tf32(aR[q].y);
                As[np][k + 2][arow] = f2tf32(aR[q].z);
                As[np][k + 3][arow] = f2tf32(aR[q].w);
            }
#pragma unroll
            for (int q = 0; q < 2; q++) {
                int nb = bcol + q * 64;
                Bs[np][brow][nb + 0] = f2tf32(bR[q].x);
                Bs[np][brow][nb + 1] = f2tf32(bR[q].y);
                Bs[np][brow][nb + 2] = f2tf32(bR[q].z);
                Bs[np][brow][nb + 3] = f2tf32(bR[q].w);
            }
            __syncthreads();
        }
    }
    // epilogue
    const int c2 = (lane & 3) * 2;
#pragma unroll
    for (int mt = 0; mt < 4; mt++) {
#pragma unroll
        for (int half = 0; half < 2; half++) {
            int row = row0 + wm + mt * 16 + r + half * 8;
            if (row < N) {
#pragma unroll
                for (int nt = 0; nt < 4; nt++) {
                    float2 v = half
                        ? make_float2(acc[mt][nt][2], acc[mt][nt][3])
                        : make_float2(acc[mt][nt][0], acc[mt][nt][1]);
                    *(float2*)(C + (size_t)row * Kc + col0 + wn + nt * 8 + c2) = v;
                }
            }
        }
    }
}

// ---------------- fused GATv2 edge pass: logit + online softmax + agg ------
// One warp per dst node. Lane l owns dims [4l..4l+3] (head hA=l>>3) in float4
// A and dims [128+4l..128+4l+3] (head hA+4) in float4 B. Next edge's xl row
// is prefetched before the shfl/exp chain (software pipeline).
// MODE 0: bias+ELU, write 256-wide h. MODE 1: head-mean + bias, 32-wide out.
template<int MODE>
__global__ void k_fused(const float* __restrict__ xl, const float* __restrict__ xr,
                        const float* __restrict__ att, const float* __restrict__ bias,
                        float* __restrict__ out) {
    int n = (blockIdx.x * blockDim.x + threadIdx.x) >> 5;
    int lane = threadIdx.x & 31;
    if (n >= NN) return;
    int beg = g_off[n], end = g_off[n + 1];

    // per-dst target transform + attention vector slices (register resident)
    const float4* xrp = (const float4*)(xr + (size_t)n * D1);
    float4 r0 = xrp[lane], r1 = xrp[32 + lane];
    float4 atA = *(const float4*)(att + 4 * lane);
    float4 atB = *(const float4*)(att + 128 + 4 * lane);

    float mA = -1e30f, mB = -1e30f, sA = 0.f, sB = 0.f;
    float4 acc0 = make_float4(0.f, 0.f, 0.f, 0.f);
    float4 acc1 = make_float4(0.f, 0.f, 0.f, 0.f);

    // prefetch first edge (every node has a self-loop, so beg < end)
    int s = __ldg(&g_srcp[beg]);
    const float4* xs = (const float4*)(xl + (size_t)s * D1);
    float4 v0 = xs[lane], v1 = xs[32 + lane];

    for (int i = beg; i < end; i++) {
        float4 cv0 = v0, cv1 = v1;
        if (i + 1 < end) {               // issue next edge's loads early
            int sn = __ldg(&g_srcp[i + 1]);
            const float4* xn = (const float4*)(xl + (size_t)sn * D1);
            v0 = xn[lane];
            v1 = xn[32 + lane];
        }
        // GATv2 logit contribution: leakyrelu(xl+xr) . att
        float z, cA, cB;
        z = cv0.x + r0.x; z = z > 0.f ? z : 0.2f * z; cA  = z * atA.x;
        z = cv0.y + r0.y; z = z > 0.f ? z : 0.2f * z; cA += z * atA.y;
        z = cv0.z + r0.z; z = z > 0.f ? z : 0.2f * z; cA += z * atA.z;
        z = cv0.w + r0.w; z = z > 0.f ? z : 0.2f * z; cA += z * atA.w;
        z = cv1.x + r1.x; z = z > 0.f ? z : 0.2f * z; cB  = z * atB.x;
        z = cv1.y + r1.y; z = z > 0.f ? z : 0.2f * z; cB += z * atB.y;
        z = cv1.z + r1.z; z = z > 0.f ? z : 0.2f * z; cB += z * atB.z;
        z = cv1.w + r1.w; z = z > 0.f ? z : 0.2f * z; cB += z * atB.w;
        // reduce within each 8-lane head group
#pragma unroll
        for (int off = 1; off < 8; off <<= 1) {
            cA += __shfl_xor_sync(0xffffffffu, cA, off);
            cB += __shfl_xor_sync(0xffffffffu, cB, off);
        }
        // online softmax update (head A)
        float mAn = fmaxf(mA, cA);
        float scA = __expf(mA - mAn);
        float pA  = __expf(cA - mAn);
        sA = sA * scA + pA;
        acc0.x = acc0.x * scA + pA * cv0.x;
        acc0.y = acc0.y * scA + pA * cv0.y;
        acc0.z = acc0.z * scA + pA * cv0.z;
        acc0.w = acc0.w * scA + pA * cv0.w;
        mA = mAn;
        // head B
        float mBn = fmaxf(mB, cB);
        float scB = __expf(mB - mBn);
        float pB  = __expf(cB - mBn);
        sB = sB * scB + pB;
        acc1.x = acc1.x * scB + pB * cv1.x;
        acc1.y = acc1.y * scB + pB * cv1.y;
        acc1.z = acc1.z * scB + pB * cv1.z;
        acc1.w = acc1.w * scB + pB * cv1.w;
        mB = mBn;
    }
    float iA = 1.f / (sA + 1e-16f);
    float iB = 1.f / (sB + 1e-16f);
    acc0.x *= iA; acc0.y *= iA; acc0.z *= iA; acc0.w *= iA;
    acc1.x *= iB; acc1.y *= iB; acc1.z *= iB; acc1.w *= iB;

    if (MODE == 1) {
        // head-mean: both float4s map to output cols 4*(lane&7)..+3; sum
        // heads across lanes {l, l^8, l^16, l^24}
        float4 tv = make_float4(acc0.x + acc1.x, acc0.y + acc1.y,
                                acc0.z + acc1.z, acc0.w + acc1.w);
#pragma unroll
        for (int off = 8; off <= 16; off <<= 1) {
            tv.x += __shfl_xor_sync(0xffffffffu, tv.x, off);
            tv.y += __shfl_xor_sync(0xffffffffu, tv.y, off);
            tv.z += __shfl_xor_sync(0xffffffffu, tv.z, off);
            tv.w += __shfl_xor_sync(0xffffffffu, tv.w, off);
        }
        if (lane < 8) {
            float4 bb = *(const float4*)(bias + lane * 4);
            float4 r = make_float4(tv.x * 0.125f + bb.x, tv.y * 0.125f + bb.y,
                                   tv.z * 0.125f + bb.z, tv.w * 0.125f + bb.w);
            *(float4*)(out + (size_t)n * 32 + lane * 4) = r;
        }
    } else {
        // fused bias + ELU for layer 1 hidden state
        float4 b0 = *(const float4*)(bias + lane * 4);
        float4 b1 = *(const float4*)(bias + 128 + lane * 4);
        float4 w0, w1;
        float v;
        v = acc0.x + b0.x; w0.x = v > 0.f ? v : expm1f(v);
        v = acc0.y + b0.y; w0.y = v > 0.f ? v : expm1f(v);
        v = acc0.z + b0.z; w0.z = v > 0.f ? v : expm1f(v);
        v = acc0.w + b0.w; w0.w = v > 0.f ? v : expm1f(v);
        v = acc1.x + b1.x; w1.x = v > 0.f ? v : expm1f(v);
        v = acc1.y + b1.y; w1.y = v > 0.f ? v : expm1f(v);
        v = acc1.z + b1.z; w1.z = v > 0.f ? v : expm1f(v);
        v = acc1.w + b1.w; w1.w = v > 0.f ? v : expm1f(v);
        float4* op = (float4*)(out + (size_t)n * D1);
        op[lane] = w0;
        op[32 + lane] = w1;
    }
}

// ---------------- launch ---------------------------------------------------
extern "C" void kernel_launch(void* const* d_in, const int* in_sizes, int n_in,
                              void* d_out, int out_size) {
    const float* x    = (const float*)d_in[0];
    const void*  ei   = d_in[1];
    const float* Wl1  = (const float*)d_in[2];
    const float* Wr1  = (const float*)d_in[3];
    const float* att1 = (const float*)d_in[4];
    const float* b1   = (const float*)d_in[5];
    const float* Wl2  = (const float*)d_in[6];
    const float* Wr2  = (const float*)d_in[7];
    const float* att2 = (const float*)d_in[8];
    const float* b2   = (const float*)d_in[9];

    float *pxl, *pxr, *ph;
    cudaGetSymbolAddress((void**)&pxl, g_xl);
    cudaGetSymbolAddress((void**)&pxr, g_xr);
    cudaGetSymbolAddress((void**)&ph,  g_h);

    // graph prep (4 launches)
    k_detect_zero<<<(NN + 255) / 256, 256>>>((const unsigned*)ei);
    k_build_count<<<(NE + 255) / 256, 256>>>(ei);
    k_scan<<<1, 1024>>>();
    k_scatter<<<(NE + 255) / 256, 256>>>();

    dim3 gg((NN + 127) / 128, 2 * D1 / 128);   // both Wl and Wr outputs
    const int ab = (NN * 32 + 255) / 256;      // warp per dst

    // layer 1
    k_gemm<<<gg, 256>>>(x, Wl1, Wr1, pxl, pxr, NN, 128, D1);
    k_fused<0><<<ab, 256>>>(pxl, pxr, att1, b1, ph);

    // layer 2
    k_gemm<<<gg, 256>>>(ph, Wl2, Wr2, pxl, pxr, NN, 256, D1);
    k_fused<1><<<ab, 256>>>(pxl, pxr, att2, b2, (float*)d_out);
}

// round 8
// speedup vs baseline: 2.3884x; 1.0110x over previous
#include <cuda_runtime.h>
#include <cstdint>
#include <math.h>

#define NN 50000
#define EE 800000
#define NE 850000      // EE + NN self loops
#define D1 256         // H*DH = H*DOUT paths both 256 wide

// ---------------- scratch (device globals; no allocation allowed) ----------
__device__ int   g_is64;
__device__ int   g_src[NE];     // edge order
__device__ int   g_dst[NE];
__device__ int   g_srcp[NE];    // CSR (dst-grouped) order
__device__ int   g_deg[NN];
__device__ int   g_off[NN + 1];
__device__ int   g_cur[NN];
__device__ float g_xl[(size_t)NN * D1];
__device__ float g_xr[(size_t)NN * D1];
__device__ float g_h [(size_t)NN * D1];

// host-side side stream + events, created once at load (no device memory)
struct AuxStreams {
    cudaStream_t s2;
    cudaEvent_t  e_fork, e_join;
    AuxStreams() {
        cudaStreamCreateWithFlags(&s2, cudaStreamNonBlocking);
        cudaEventCreateWithFlags(&e_fork, cudaEventDisableTiming);
        cudaEventCreateWithFlags(&e_join, cudaEventDisableTiming);
    }
};
static AuxStreams g_aux;

// ---------------- detect dtype (block 0) + zero degree array ---------------
__global__ void k_detect_zero(const unsigned* __restrict__ p) {
    int i = blockIdx.x * blockDim.x + threadIdx.x;
    if (i < NN) g_deg[i] = 0;
    if (blockIdx.x == 0) {
        __shared__ unsigned acc;
        if (threadIdx.x == 0) acc = 0u;
        __syncthreads();
        if (threadIdx.x < 128) {
            unsigned v = p[threadIdx.x * 2 + 1];
            if (v) atomicOr(&acc, 1u);
        }
        __syncthreads();
        if (threadIdx.x == 0) g_is64 = (acc == 0u) ? 1 : 0;
    }
}

// ---------------- build src/dst with self loops + degree count -------------
__global__ void k_build_count(const void* __restrict__ ei) {
    int i = blockIdx.x * blockDim.x + threadIdx.x;
    if (i >= NE) return;
    int s, d;
    if (i < EE) {
        if (g_is64) {
            const long long* p = (const long long*)ei;
            s = (int)p[i];
            d = (int)p[EE + i];
        } else {
            const int* p = (const int*)ei;
            s = p[i];
            d = p[EE + i];
        }
    } else {
        s = d = i - EE;
    }
    g_src[i] = s;
    g_dst[i] = d;
    atomicAdd(&g_deg[d], 1);
}

// single-block exclusive scan over 50000 counts
__global__ void k_scan() {
    const int T = 1024, CH = 49;     // 1024*49 = 50176 >= NN
    __shared__ int sm[T];
    int t = threadIdx.x;
    int beg = t * CH, end = min(beg + CH, NN);
    int s = 0;
    for (int i = beg; i < end; i++) s += g_deg[i];
    sm[t] = s;
    __syncthreads();
    for (int off = 1; off < T; off <<= 1) {
        int v = (t >= off) ? sm[t - off] : 0;
        __syncthreads();
        sm[t] += v;
        __syncthreads();
    }
    int run = sm[t] - s;            // exclusive prefix
    for (int i = beg; i < end; i++) {
        g_off[i] = run;
        g_cur[i] = run;
        run += g_deg[i];
    }
    if (t == T - 1) g_off[NN] = sm[T - 1];
}

__global__ void k_scatter() {
    int i = blockIdx.x * blockDim.x + threadIdx.x;
    if (i >= NE) return;
    int p = atomicAdd(&g_cur[g_dst[i]], 1);
    g_srcp[p] = g_src[i];
}

// ---------------- tf32 tensor-core GEMM, double-buffered, 2 CTA/SM ---------
// C0 = A[N,M] @ W0[M,Kc], C1 = A @ W1 (blockIdx.y selects). 128x128 tile,
// 256 threads (8 warps as 2m x 4n, warp tile 64x32), K-chunk 16.
// smem = 33.8 KB -> two CTAs co-resident per SM for latency hiding.
__device__ __forceinline__ unsigned f2tf32(float x) {
    unsigned r;
    asm("cvt.rna.tf32.f32 %0, %1;" : "=r"(r) : "f"(x));
    return r;
}
__device__ __forceinline__ void mma_tf32(float* c, unsigned a0, unsigned a1,
                                         unsigned a2, unsigned a3,
                                         unsigned b0, unsigned b1) {
    asm volatile(
        "mma.sync.aligned.m16n8k8.row.col.f32.tf32.tf32.f32 "
        "{%0,%1,%2,%3}, {%4,%5,%6,%7}, {%8,%9}, {%0,%1,%2,%3};"
        : "+f"(c[0]), "+f"(c[1]), "+f"(c[2]), "+f"(c[3])
        : "r"(a0), "r"(a1), "r"(a2), "r"(a3), "r"(b0), "r"(b1));
}

__global__ __launch_bounds__(256, 2)
void k_gemm(const float* __restrict__ A,
            const float* __restrict__ W0, const float* __restrict__ W1,
            float* __restrict__ C0, float* __restrict__ C1,
            int N, int M, int Kc) {
    __shared__ unsigned As[2][16][132];   // [buf][k][m] padded
    __shared__ unsigned Bs[2][16][132];   // [buf][k][n]
    const int t = threadIdx.x;
    const int lane = t & 31, warp = t >> 5;
    const int wm = (warp >> 2) << 6;   // 0 / 64
    const int wn = (warp & 3) << 5;    // 0..96
    const int row0 = blockIdx.x * 128;
    int col0 = blockIdx.y * 128;
    const float* W = W0;
    float* C = C0;
    if (col0 >= Kc) { col0 -= Kc; W = W1; C = C1; }

    float acc[4][4][4];
#pragma unroll
    for (int mt = 0; mt < 4; mt++)
#pragma unroll
        for (int nt = 0; nt < 4; nt++)
#pragma unroll
            for (int j = 0; j < 4; j++) acc[mt][nt][j] = 0.f;

    const int arow = t >> 1;             // 0..127
    const int ak   = (t & 1) * 8;        // 0 / 8 float offset in chunk
    const int brow = t >> 4;             // 0..15 (k)
    const int bcol = (t & 15) * 4;       // n offset; second float4 at +64
    const bool aok = (row0 + arow) < N;

    float4 aR[2], bR[2];
    {   // chunk 0: load + store to buffer 0
        const float* ap = A + (size_t)(row0 + arow) * M + ak;
#pragma unroll
        for (int q = 0; q < 2; q++)
            aR[q] = aok ? *(const float4*)(ap + q * 4)
                        : make_float4(0.f, 0.f, 0.f, 0.f);
        const float* bp = W + (size_t)brow * Kc + col0 + bcol;
#pragma unroll
        for (int q = 0; q < 2; q++)
            bR[q] = *(const float4*)(bp + q * 64);
#pragma unroll
        for (int q = 0; q < 2; q++) {
            int k = ak + q * 4;
            As[0][k + 0][arow] = f2tf32(aR[q].x);
            As[0][k + 1][arow] = f2tf32(aR[q].y);
            As[0][k + 2][arow] = f2tf32(aR[q].z);
            As[0][k + 3][arow] = f2tf32(aR[q].w);
        }
#pragma unroll
        for (int q = 0; q < 2; q++) {
            int nb = bcol + q * 64;
            Bs[0][brow][nb + 0] = f2tf32(bR[q].x);
            Bs[0][brow][nb + 1] = f2tf32(bR[q].y);
            Bs[0][brow][nb + 2] = f2tf32(bR[q].z);
            Bs[0][brow][nb + 3] = f2tf32(bR[q].w);
        }
    }
    __syncthreads();

    const int nchunk = M >> 4;
    const int r = lane >> 2, c = lane & 3;
    for (int ch = 0; ch < nchunk; ch++) {
        int p = ch & 1;
        bool more = (ch + 1 < nchunk);
        if (more) {                      // issue next chunk's global loads now
            int k0 = (ch + 1) << 4;
            const float* ap = A + (size_t)(row0 + arow) * M + k0 + ak;
#pragma unroll
            for (int q = 0; q < 2; q++)
                aR[q] = aok ? *(const float4*)(ap + q * 4)
                            : make_float4(0.f, 0.f, 0.f, 0.f);
            const float* bp = W + (size_t)(k0 + brow) * Kc + col0 + bcol;
#pragma unroll
            for (int q = 0; q < 2; q++)
                bR[q] = *(const float4*)(bp + q * 64);
        }
        // compute from buffer p (hides the global load latency above)
#pragma unroll
        for (int ks = 0; ks < 2; ks++) {
            int k = ks * 8;
            unsigned a[4][4], b[4][2];
#pragma unroll
            for (int mt = 0; mt < 4; mt++) {
                int mb = wm + mt * 16 + r;
                a[mt][0] = As[p][k + c][mb];
                a[mt][1] = As[p][k + c][mb + 8];
                a[mt][2] = As[p][k + c + 4][mb];
                a[mt][3] = As[p][k + c + 4][mb + 8];
            }
#pragma unroll
            for (int nt = 0; nt < 4; nt++) {
                int nb = wn + nt * 8 + r;
                b[nt][0] = Bs[p][k + c][nb];
                b[nt][1] = Bs[p][k + c + 4][nb];
            }
#pragma unroll
            for (int mt = 0; mt < 4; mt++)
#pragma unroll
                for (int nt = 0; nt < 4; nt++)
                    mma_tf32(acc[mt][nt], a[mt][0], a[mt][1], a[mt][2],
                             a[mt][3], b[nt][0], b[nt][1]);
        }
        if (more) {                      // store next chunk to other buffer
            int np = p ^ 1;
#pragma unroll
            for (int q = 0; q < 2; q++) {
                int k = ak + q * 4;
                As[np][k + 0][arow] = f2tf32(aR[q].x);
                As[np][k + 1][arow] = f2tf32(aR[q].y);
                As[np][k + 2][arow] = f2tf32(aR[q].z);
                As[np][k + 3][arow] = f2tf32(aR[q].w);
            }
#pragma unroll
            for (int q = 0; q < 2; q++) {
                int nb = bcol + q * 64;
                Bs[np][brow][nb + 0] = f2tf32(bR[q].x);
                Bs[np][brow][nb + 1] = f2tf32(bR[q].y);
                Bs[np][brow][nb + 2] = f2tf32(bR[q].z);
                Bs[np][brow][nb + 3] = f2tf32(bR[q].w);
            }
            __syncthreads();
        }
    }
    // epilogue
    const int c2 = (lane & 3) * 2;
#pragma unroll
    for (int mt = 0; mt < 4; mt++) {
#pragma unroll
        for (int half = 0; half < 2; half++) {
            int row = row0 + wm + mt * 16 + r + half * 8;
            if (row < N) {
#pragma unroll
                for (int nt = 0; nt < 4; nt++) {
                    float2 v = half
                        ? make_float2(acc[mt][nt][2], acc[mt][nt][3])
                        : make_float2(acc[mt][nt][0], acc[mt][nt][1]);
                    *(float2*)(C + (size_t)row * Kc + col0 + wn + nt * 8 + c2) = v;
                }
            }
        }
    }
}

// ---------------- fused GATv2 edge pass: logit + online softmax + agg ------
// One warp per dst node. Lane l owns dims [4l..4l+3] (head hA=l>>3) in float4
// A and dims [128+4l..128+4l+3] (head hA+4) in float4 B. Next edge's xl row
// is prefetched before the shfl/exp chain (software pipeline).
// MODE 0: bias+ELU, write 256-wide h. MODE 1: head-mean + bias, 32-wide out.
template<int MODE>
__global__ void k_fused(const float* __restrict__ xl, const float* __restrict__ xr,
                        const float* __restrict__ att, const float* __restrict__ bias,
                        float* __restrict__ out) {
    int n = (blockIdx.x * blockDim.x + threadIdx.x) >> 5;
    int lane = threadIdx.x & 31;
    if (n >= NN) return;
    int beg = g_off[n], end = g_off[n + 1];

    // per-dst target transform + attention vector slices (register resident)
    const float4* xrp = (const float4*)(xr + (size_t)n * D1);
    float4 r0 = xrp[lane], r1 = xrp[32 + lane];
    float4 atA = *(const float4*)(att + 4 * lane);
    float4 atB = *(const float4*)(att + 128 + 4 * lane);

    float mA = -1e30f, mB = -1e30f, sA = 0.f, sB = 0.f;
    float4 acc0 = make_float4(0.f, 0.f, 0.f, 0.f);
    float4 acc1 = make_float4(0.f, 0.f, 0.f, 0.f);

    // prefetch first edge (every node has a self-loop, so beg < end)
    int s = __ldg(&g_srcp[beg]);
    const float4* xs = (const float4*)(xl + (size_t)s * D1);
    float4 v0 = xs[lane], v1 = xs[32 + lane];

    for (int i = beg; i < end; i++) {
        float4 cv0 = v0, cv1 = v1;
        if (i + 1 < end) {               // issue next edge's loads early
            int sn = __ldg(&g_srcp[i + 1]);
            const float4* xn = (const float4*)(xl + (size_t)sn * D1);
            v0 = xn[lane];
            v1 = xn[32 + lane];
        }
        // GATv2 logit contribution: leakyrelu(xl+xr) . att
        float z, cA, cB;
        z = cv0.x + r0.x; z = z > 0.f ? z : 0.2f * z; cA  = z * atA.x;
        z = cv0.y + r0.y; z = z > 0.f ? z : 0.2f * z; cA += z * atA.y;
        z = cv0.z + r0.z; z = z > 0.f ? z : 0.2f * z; cA += z * atA.z;
        z = cv0.w + r0.w; z = z > 0.f ? z : 0.2f * z; cA += z * atA.w;
        z = cv1.x + r1.x; z = z > 0.f ? z : 0.2f * z; cB  = z * atB.x;
        z = cv1.y + r1.y; z = z > 0.f ? z : 0.2f * z; cB += z * atB.y;
        z = cv1.z + r1.z; z = z > 0.f ? z : 0.2f * z; cB += z * atB.z;
        z = cv1.w + r1.w; z = z > 0.f ? z : 0.2f * z; cB += z * atB.w;
        // reduce within each 8-lane head group
#pragma unroll
        for (int off = 1; off < 8; off <<= 1) {
            cA += __shfl_xor_sync(0xffffffffu, cA, off);
            cB += __shfl_xor_sync(0xffffffffu, cB, off);
        }
        // online softmax update (head A)
        float mAn = fmaxf(mA, cA);
        float scA = __expf(mA - mAn);
        float pA  = __expf(cA - mAn);
        sA = sA * scA + pA;
        acc0.x = acc0.x * scA + pA * cv0.x;
        acc0.y = acc0.y * scA + pA * cv0.y;
        acc0.z = acc0.z * scA + pA * cv0.z;
        acc0.w = acc0.w * scA + pA * cv0.w;
        mA = mAn;
        // head B
        float mBn = fmaxf(mB, cB);
        float scB = __expf(mB - mBn);
        float pB  = __expf(cB - mBn);
        sB = sB * scB + pB;
        acc1.x = acc1.x * scB + pB * cv1.x;
        acc1.y = acc1.y * scB + pB * cv1.y;
        acc1.z = acc1.z * scB + pB * cv1.z;
        acc1.w = acc1.w * scB + pB * cv1.w;
        mB = mBn;
    }
    float iA = 1.f / (sA + 1e-16f);
    float iB = 1.f / (sB + 1e-16f);
    acc0.x *= iA; acc0.y *= iA; acc0.z *= iA; acc0.w *= iA;
    acc1.x *= iB; acc1.y *= iB; acc1.z *= iB; acc1.w *= iB;

    if (MODE == 1) {
        // head-mean: both float4s map to output cols 4*(lane&7)..+3; sum
        // heads across lanes {l, l^8, l^16, l^24}
        float4 tv = make_float4(acc0.x + acc1.x, acc0.y + acc1.y,
                                acc0.z + acc1.z, acc0.w + acc1.w);
#pragma unroll
        for (int off = 8; off <= 16; off <<= 1) {
            tv.x += __shfl_xor_sync(0xffffffffu, tv.x, off);
            tv.y += __shfl_xor_sync(0xffffffffu, tv.y, off);
            tv.z += __shfl_xor_sync(0xffffffffu, tv.z, off);
            tv.w += __shfl_xor_sync(0xffffffffu, tv.w, off);
        }
        if (lane < 8) {
            float4 bb = *(const float4*)(bias + lane * 4);
            float4 r = make_float4(tv.x * 0.125f + bb.x, tv.y * 0.125f + bb.y,
                                   tv.z * 0.125f + bb.z, tv.w * 0.125f + bb.w);
            *(float4*)(out + (size_t)n * 32 + lane * 4) = r;
        }
    } else {
        // fused bias + ELU for layer 1 hidden state
        float4 b0 = *(const float4*)(bias + lane * 4);
        float4 b1 = *(const float4*)(bias + 128 + lane * 4);
        float4 w0, w1;
        float v;
        v = acc0.x + b0.x; w0.x = v > 0.f ? v : expm1f(v);
        v = acc0.y + b0.y; w0.y = v > 0.f ? v : expm1f(v);
        v = acc0.z + b0.z; w0.z = v > 0.f ? v : expm1f(v);
        v = acc0.w + b0.w; w0.w = v > 0.f ? v : expm1f(v);
        v = acc1.x + b1.x; w1.x = v > 0.f ? v : expm1f(v);
        v = acc1.y + b1.y; w1.y = v > 0.f ? v : expm1f(v);
        v = acc1.z + b1.z; w1.z = v > 0.f ? v : expm1f(v);
        v = acc1.w + b1.w; w1.w = v > 0.f ? v : expm1f(v);
        float4* op = (float4*)(out + (size_t)n * D1);
        op[lane] = w0;
        op[32 + lane] = w1;
    }
}

// ---------------- launch ---------------------------------------------------
extern "C" void kernel_launch(void* const* d_in, const int* in_sizes, int n_in,
                              void* d_out, int out_size) {
    const float* x    = (const float*)d_in[0];
    const void*  ei   = d_in[1];
    const float* Wl1  = (const float*)d_in[2];
    const float* Wr1  = (const float*)d_in[3];
    const float* att1 = (const float*)d_in[4];
    const float* b1   = (const float*)d_in[5];
    const float* Wl2  = (const float*)d_in[6];
    const float* Wr2  = (const float*)d_in[7];
    const float* att2 = (const float*)d_in[8];
    const float* b2   = (const float*)d_in[9];

    float *pxl, *pxr, *ph;
    cudaGetSymbolAddress((void**)&pxl, g_xl);
    cudaGetSymbolAddress((void**)&pxr, g_xr);
    cudaGetSymbolAddress((void**)&ph,  g_h);

    dim3 gg((NN + 127) / 128, 2 * D1 / 128);   // both Wl and Wr outputs
    const int ab = (NN * 32 + 255) / 256;      // warp per dst

    // fork: layer-1 GEMM (depends only on x/Wl1/Wr1) runs on side stream,
    // concurrent with the graph-prep chain on the main stream.
    cudaEventRecord(g_aux.e_fork, 0);
    cudaStreamWaitEvent(g_aux.s2, g_aux.e_fork, 0);
    k_gemm<<<gg, 256, 0, g_aux.s2>>>(x, Wl1, Wr1, pxl, pxr, NN, 128, D1);
    cudaEventRecord(g_aux.e_join, g_aux.s2);

    // graph prep (main stream, overlapped with GEMM1)
    k_detect_zero<<<(NN + 255) / 256, 256>>>((const unsigned*)ei);
    k_build_count<<<(NE + 255) / 256, 256>>>(ei);
    k_scan<<<1, 1024>>>();
    k_scatter<<<(NE + 255) / 256, 256>>>();

    // join: fused layer 1 needs both GEMM1 outputs and the CSR
    cudaStreamWaitEvent(0, g_aux.e_join, 0);
    k_fused<0><<<ab, 256>>>(pxl, pxr, att1, b1, ph);

    // layer 2 (serial dependence)
    k_gemm<<<gg, 256>>>(ph, Wl2, Wr2, pxl, pxr, NN, 256, D1);
    k_fused<1><<<ab, 256>>>(pxl, pxr, att2, b2, (float*)d_out);
}

// round 9
// speedup vs baseline: 2.7241x; 1.1406x over previous
#include <cuda_runtime.h>
#include <cstdint>
#include <math.h>

#define NN 50000
#define EE 800000
#define NE 850000      // EE + NN self loops
#define D1 256         // H*DH = H*DOUT paths both 256 wide

#define SCAN_CH 256
#define SCAN_NB ((NN + SCAN_CH - 1) / SCAN_CH)   // 196

// ---------------- scratch (device globals; no allocation allowed) ----------
__device__ int   g_is64;
__device__ int   g_src[NE];     // edge order
__device__ int   g_dst[NE];
__device__ int   g_srcp[NE];    // CSR (dst-grouped) order
__device__ int   g_deg[NN];
__device__ int   g_off[NN + 1];
__device__ int   g_cur[NN];
__device__ int   g_bsum[SCAN_NB];
__device__ float g_xl[(size_t)NN * D1];
__device__ float g_xr[(size_t)NN * D1];
__device__ float g_h [(size_t)NN * D1];

// host-side side stream + events, created once at load (no device memory)
struct AuxStreams {
    cudaStream_t s2;
    cudaEvent_t  e_fork, e_join;
    AuxStreams() {
        cudaStreamCreateWithFlags(&s2, cudaStreamNonBlocking);
        cudaEventCreateWithFlags(&e_fork, cudaEventDisableTiming);
        cudaEventCreateWithFlags(&e_join, cudaEventDisableTiming);
    }
};
static AuxStreams g_aux;

// ---------------- detect dtype (block 0) + zero degree array ---------------
__global__ void k_detect_zero(const unsigned* __restrict__ p) {
    int i = blockIdx.x * blockDim.x + threadIdx.x;
    if (i < NN) g_deg[i] = 0;
    if (blockIdx.x == 0) {
        __shared__ unsigned acc;
        if (threadIdx.x == 0) acc = 0u;
        __syncthreads();
        if (threadIdx.x < 128) {
            unsigned v = p[threadIdx.x * 2 + 1];
            if (v) atomicOr(&acc, 1u);
        }
        __syncthreads();
        if (threadIdx.x == 0) g_is64 = (acc == 0u) ? 1 : 0;
    }
}

// ---------------- build src/dst with self loops + degree count -------------
__global__ void k_build_count(const void* __restrict__ ei) {
    int i = blockIdx.x * blockDim.x + threadIdx.x;
    if (i >= NE) return;
    int s, d;
    if (i < EE) {
        if (g_is64) {
            const long long* p = (const long long*)ei;
            s = (int)p[i];
            d = (int)p[EE + i];
        } else {
            const int* p = (const int*)ei;
            s = p[i];
            d = p[EE + i];
        }
    } else {
        s = d = i - EE;
    }
    g_src[i] = s;
    g_dst[i] = d;
    atomicAdd(&g_deg[d], 1);
}

// ---------------- 3-phase multi-block exclusive scan -----------------------
__global__ void k_scan1() {
    __shared__ int sm[SCAN_CH];
    int b = blockIdx.x, t = threadIdx.x;
    int i = b * SCAN_CH + t;
    int v = (i < NN) ? g_deg[i] : 0;
    sm[t] = v;
    __syncthreads();
#pragma unroll
    for (int off = 1; off < SCAN_CH; off <<= 1) {
        int u = (t >= off) ? sm[t - off] : 0;
        __syncthreads();
        sm[t] += u;
        __syncthreads();
    }
    if (i < NN) g_off[i] = sm[t] - v;           // exclusive within block
    if (t == SCAN_CH - 1) g_bsum[b] = sm[t];    // block total
}

__global__ void k_scan2() {
    __shared__ int sm[256];
    int t = threadIdx.x;
    int v = (t < SCAN_NB) ? g_bsum[t] : 0;
    sm[t] = v;
    __syncthreads();
#pragma unroll
    for (int off = 1; off < 256; off <<= 1) {
        int u = (t >= off) ? sm[t - off] : 0;
        __syncthreads();
        sm[t] += u;
        __syncthreads();
    }
    if (t < SCAN_NB) g_bsum[t] = sm[t] - v;     // exclusive block offsets
    if (t == 255) g_off[NN] = sm[255];          // grand total (== NE)
}

__global__ void k_scan3() {
    int i = blockIdx.x * blockDim.x + threadIdx.x;
    if (i >= NN) return;
    int o = g_off[i] + g_bsum[i >> 8];          // SCAN_CH == 256
    g_off[i] = o;
    g_cur[i] = o;
}

__global__ void k_scatter() {
    int i = blockIdx.x * blockDim.x + threadIdx.x;
    if (i >= NE) return;
    int p = atomicAdd(&g_cur[g_dst[i]], 1);
    g_srcp[p] = g_src[i];
}

// ---------------- tf32 tensor-core GEMM, double-buffered, 2 CTA/SM ---------
// C0 = A[N,M] @ W0[M,Kc], C1 = A @ W1 (blockIdx.y selects). 128x128 tile,
// 256 threads (8 warps as 2m x 4n, warp tile 64x32), K-chunk 16.
// smem = 33.8 KB -> two CTAs co-resident per SM for latency hiding.
__device__ __forceinline__ unsigned f2tf32(float x) {
    unsigned r;
    asm("cvt.rna.tf32.f32 %0, %1;" : "=r"(r) : "f"(x));
    return r;
}
__device__ __forceinline__ void mma_tf32(float* c, unsigned a0, unsigned a1,
                                         unsigned a2, unsigned a3,
                                         unsigned b0, unsigned b1) {
    asm volatile(
        "mma.sync.aligned.m16n8k8.row.col.f32.tf32.tf32.f32 "
        "{%0,%1,%2,%3}, {%4,%5,%6,%7}, {%8,%9}, {%0,%1,%2,%3};"
        : "+f"(c[0]), "+f"(c[1]), "+f"(c[2]), "+f"(c[3])
        : "r"(a0), "r"(a1), "r"(a2), "r"(a3), "r"(b0), "r"(b1));
}

__global__ __launch_bounds__(256, 2)
void k_gemm(const float* __restrict__ A,
            const float* __restrict__ W0, const float* __restrict__ W1,
            float* __restrict__ C0, float* __restrict__ C1,
            int N, int M, int Kc) {
    __shared__ unsigned As[2][16][132];   // [buf][k][m] padded
    __shared__ unsigned Bs[2][16][132];   // [buf][k][n]
    const int t = threadIdx.x;
    const int lane = t & 31, warp = t >> 5;
    const int wm = (warp >> 2) << 6;   // 0 / 64
    const int wn = (warp & 3) << 5;    // 0..96
    const int row0 = blockIdx.x * 128;
    int col0 = blockIdx.y * 128;
    const float* W = W0;
    float* C = C0;
    if (col0 >= Kc) { col0 -= Kc; W = W1; C = C1; }

    float acc[4][4][4];
#pragma unroll
    for (int mt = 0; mt < 4; mt++)
#pragma unroll
        for (int nt = 0; nt < 4; nt++)
#pragma unroll
            for (int j = 0; j < 4; j++) acc[mt][nt][j] = 0.f;

    const int arow = t >> 1;             // 0..127
    const int ak   = (t & 1) * 8;        // 0 / 8 float offset in chunk
    const int brow = t >> 4;             // 0..15 (k)
    const int bcol = (t & 15) * 4;       // n offset; second float4 at +64
    const bool aok = (row0 + arow) < N;

    float4 aR[2], bR[2];
    {   // chunk 0: load + store to buffer 0
        const float* ap = A + (size_t)(row0 + arow) * M + ak;
#pragma unroll
        for (int q = 0; q < 2; q++)
            aR[q] = aok ? *(const float4*)(ap + q * 4)
                        : make_float4(0.f, 0.f, 0.f, 0.f);
        const float* bp = W + (size_t)brow * Kc + col0 + bcol;
#pragma unroll
        for (int q = 0; q < 2; q++)
            bR[q] = *(const float4*)(bp + q * 64);
#pragma unroll
        for (int q = 0; q < 2; q++) {
            int k = ak + q * 4;
            As[0][k + 0][arow] = f2tf32(aR[q].x);
            As[0][k + 1][arow] = f2tf32(aR[q].y);
            As[0][k + 2][arow] = f2tf32(aR[q].z);
            As[0][k + 3][arow] = f2tf32(aR[q].w);
        }
#pragma unroll
        for (int q = 0; q < 2; q++) {
            int nb = bcol + q * 64;
            Bs[0][brow][nb + 0] = f2tf32(bR[q].x);
            Bs[0][brow][nb + 1] = f2tf32(bR[q].y);
            Bs[0][brow][nb + 2] = f2tf32(bR[q].z);
            Bs[0][brow][nb + 3] = f2tf32(bR[q].w);
        }
    }
    __syncthreads();

    const int nchunk = M >> 4;
    const int r = lane >> 2, c = lane & 3;
    for (int ch = 0; ch < nchunk; ch++) {
        int p = ch & 1;
        bool more = (ch + 1 < nchunk);
        if (more) {                      // issue next chunk's global loads now
            int k0 = (ch + 1) << 4;
            const float* ap = A + (size_t)(row0 + arow) * M + k0 + ak;
#pragma unroll
            for (int q = 0; q < 2; q++)
                aR[q] = aok ? *(const float4*)(ap + q * 4)
                            : make_float4(0.f, 0.f, 0.f, 0.f);
            const float* bp = W + (size_t)(k0 + brow) * Kc + col0 + bcol;
#pragma unroll
            for (int q = 0; q < 2; q++)
                bR[q] = *(const float4*)(bp + q * 64);
        }
        // compute from buffer p (hides the global load latency above)
#pragma unroll
        for (int ks = 0; ks < 2; ks++) {
            int k = ks * 8;
            unsigned a[4][4], b[4][2];
#pragma unroll
            for (int mt = 0; mt < 4; mt++) {
                int mb = wm + mt * 16 + r;
                a[mt][0] = As[p][k + c][mb];
                a[mt][1] = As[p][k + c][mb + 8];
                a[mt][2] = As[p][k + c + 4][mb];
                a[mt][3] = As[p][k + c + 4][mb + 8];
            }
#pragma unroll
            for (int nt = 0; nt < 4; nt++) {
                int nb = wn + nt * 8 + r;
                b[nt][0] = Bs[p][k + c][nb];
                b[nt][1] = Bs[p][k + c + 4][nb];
            }
#pragma unroll
            for (int mt = 0; mt < 4; mt++)
#pragma unroll
                for (int nt = 0; nt < 4; nt++)
                    mma_tf32(acc[mt][nt], a[mt][0], a[mt][1], a[mt][2],
                             a[mt][3], b[nt][0], b[nt][1]);
        }
        if (more) {                      // store next chunk to other buffer
            int np = p ^ 1;
#pragma unroll
            for (int q = 0; q < 2; q++) {
                int k = ak + q * 4;
                As[np][k + 0][arow] = f2tf32(aR[q].x);
                As[np][k + 1][arow] = f2tf32(aR[q].y);
                As[np][k + 2][arow] = f2tf32(aR[q].z);
                As[np][k + 3][arow] = f2tf32(aR[q].w);
            }
#pragma unroll
            for (int q = 0; q < 2; q++) {
                int nb = bcol + q * 64;
                Bs[np][brow][nb + 0] = f2tf32(bR[q].x);
                Bs[np][brow][nb + 1] = f2tf32(bR[q].y);
                Bs[np][brow][nb + 2] = f2tf32(bR[q].z);
                Bs[np][brow][nb + 3] = f2tf32(bR[q].w);
            }
            __syncthreads();
        }
    }
    // epilogue
    const int c2 = (lane & 3) * 2;
#pragma unroll
    for (int mt = 0; mt < 4; mt++) {
#pragma unroll
        for (int half = 0; half < 2; half++) {
            int row = row0 + wm + mt * 16 + r + half * 8;
            if (row < N) {
#pragma unroll
                for (int nt = 0; nt < 4; nt++) {
                    float2 v = half
                        ? make_float2(acc[mt][nt][2], acc[mt][nt][3])
                        : make_float2(acc[mt][nt][0], acc[mt][nt][1]);
                    *(float2*)(C + (size_t)row * Kc + col0 + wn + nt * 8 + c2) = v;
                }
            }
        }
    }
}

// ---------------- fused GATv2 edge pass: logit + online softmax + agg ------
// One warp per dst node. Lane l owns dims [4l..4l+3] (head hA=l>>3) in float4
// A and dims [128+4l..128+4l+3] (head hA+4) in float4 B. Next edge's xl row
// is prefetched before the shfl/exp chain (software pipeline).
// MODE 0: bias+ELU, write 256-wide h. MODE 1: head-mean + bias, 32-wide out.
template<int MODE>
__global__ void k_fused(const float* __restrict__ xl, const float* __restrict__ xr,
                        const float* __restrict__ att, const float* __restrict__ bias,
                        float* __restrict__ out) {
    int n = (blockIdx.x * blockDim.x + threadIdx.x) >> 5;
    int lane = threadIdx.x & 31;
    if (n >= NN) return;
    int beg = g_off[n], end = g_off[n + 1];

    // per-dst target transform + attention vector slices (register resident)
    const float4* xrp = (const float4*)(xr + (size_t)n * D1);
    float4 r0 = xrp[lane], r1 = xrp[32 + lane];
    float4 atA = *(const float4*)(att + 4 * lane);
    float4 atB = *(const float4*)(att + 128 + 4 * lane);

    float mA = -1e30f, mB = -1e30f, sA = 0.f, sB = 0.f;
    float4 acc0 = make_float4(0.f, 0.f, 0.f, 0.f);
    float4 acc1 = make_float4(0.f, 0.f, 0.f, 0.f);

    // prefetch first edge (every node has a self-loop, so beg < end)
    int s = __ldg(&g_srcp[beg]);
    const float4* xs = (const float4*)(xl + (size_t)s * D1);
    float4 v0 = xs[lane], v1 = xs[32 + lane];

    for (int i = beg; i < end; i++) {
        float4 cv0 = v0, cv1 = v1;
        if (i + 1 < end) {               // issue next edge's loads early
            int sn = __ldg(&g_srcp[i + 1]);
            const float4* xn = (const float4*)(xl + (size_t)sn * D1);
            v0 = xn[lane];
            v1 = xn[32 + lane];
        }
        // GATv2 logit contribution: leakyrelu(xl+xr) . att
        float z, cA, cB;
        z = cv0.x + r0.x; z = z > 0.f ? z : 0.2f * z; cA  = z * atA.x;
        z = cv0.y + r0.y; z = z > 0.f ? z : 0.2f * z; cA += z * atA.y;
        z = cv0.z + r0.z; z = z > 0.f ? z : 0.2f * z; cA += z * atA.z;
        z = cv0.w + r0.w; z = z > 0.f ? z : 0.2f * z; cA += z * atA.w;
        z = cv1.x + r1.x; z = z > 0.f ? z : 0.2f * z; cB  = z * atB.x;
        z = cv1.y + r1.y; z = z > 0.f ? z : 0.2f * z; cB += z * atB.y;
        z = cv1.z + r1.z; z = z > 0.f ? z : 0.2f * z; cB += z * atB.z;
        z = cv1.w + r1.w; z = z > 0.f ? z : 0.2f * z; cB += z * atB.w;
        // reduce within each 8-lane head group
#pragma unroll
        for (int off = 1; off < 8; off <<= 1) {
            cA += __shfl_xor_sync(0xffffffffu, cA, off);
            cB += __shfl_xor_sync(0xffffffffu, cB, off);
        }
        // online softmax update (head A)
        float mAn = fmaxf(mA, cA);
        float scA = __expf(mA - mAn);
        float pA  = __expf(cA - mAn);
        sA = sA * scA + pA;
        acc0.x = acc0.x * scA + pA * cv0.x;
        acc0.y = acc0.y * scA + pA * cv0.y;
        acc0.z = acc0.z * scA + pA * cv0.z;
        acc0.w = acc0.w * scA + pA * cv0.w;
        mA = mAn;
        // head B
        float mBn = fmaxf(mB, cB);
        float scB = __expf(mB - mBn);
        float pB  = __expf(cB - mBn);
        sB = sB * scB + pB;
        acc1.x = acc1.x * scB + pB * cv1.x;
        acc1.y = acc1.y * scB + pB * cv1.y;
        acc1.z = acc1.z * scB + pB * cv1.z;
        acc1.w = acc1.w * scB + pB * cv1.w;
        mB = mBn;
    }
    float iA = 1.f / (sA + 1e-16f);
    float iB = 1.f / (sB + 1e-16f);
    acc0.x *= iA; acc0.y *= iA; acc0.z *= iA; acc0.w *= iA;
    acc1.x *= iB; acc1.y *= iB; acc1.z *= iB; acc1.w *= iB;

    if (MODE == 1) {
        // head-mean: both float4s map to output cols 4*(lane&7)..+3; sum
        // heads across lanes {l, l^8, l^16, l^24}
        float4 tv = make_float4(acc0.x + acc1.x, acc0.y + acc1.y,
                                acc0.z + acc1.z, acc0.w + acc1.w);
#pragma unroll
        for (int off = 8; off <= 16; off <<= 1) {
            tv.x += __shfl_xor_sync(0xffffffffu, tv.x, off);
            tv.y += __shfl_xor_sync(0xffffffffu, tv.y, off);
            tv.z += __shfl_xor_sync(0xffffffffu, tv.z, off);
            tv.w += __shfl_xor_sync(0xffffffffu, tv.w, off);
        }
        if (lane < 8) {
            float4 bb = *(const float4*)(bias + lane * 4);
            float4 r = make_float4(tv.x * 0.125f + bb.x, tv.y * 0.125f + bb.y,
                                   tv.z * 0.125f + bb.z, tv.w * 0.125f + bb.w);
            *(float4*)(out + (size_t)n * 32 + lane * 4) = r;
        }
    } else {
        // fused bias + ELU for layer 1 hidden state
        float4 b0 = *(const float4*)(bias + lane * 4);
        float4 b1 = *(const float4*)(bias + 128 + lane * 4);
        float4 w0, w1;
        float v;
        v = acc0.x + b0.x; w0.x = v > 0.f ? v : expm1f(v);
        v = acc0.y + b0.y; w0.y = v > 0.f ? v : expm1f(v);
        v = acc0.z + b0.z; w0.z = v > 0.f ? v : expm1f(v);
        v = acc0.w + b0.w; w0.w = v > 0.f ? v : expm1f(v);
        v = acc1.x + b1.x; w1.x = v > 0.f ? v : expm1f(v);
        v = acc1.y + b1.y; w1.y = v > 0.f ? v : expm1f(v);
        v = acc1.z + b1.z; w1.z = v > 0.f ? v : expm1f(v);
        v = acc1.w + b1.w; w1.w = v > 0.f ? v : expm1f(v);
        float4* op = (float4*)(out + (size_t)n * D1);
        op[lane] = w0;
        op[32 + lane] = w1;
    }
}

// ---------------- launch ---------------------------------------------------
extern "C" void kernel_launch(void* const* d_in, const int* in_sizes, int n_in,
                              void* d_out, int out_size) {
    const float* x    = (const float*)d_in[0];
    const void*  ei   = d_in[1];
    const float* Wl1  = (const float*)d_in[2];
    const float* Wr1  = (const float*)d_in[3];
    const float* att1 = (const float*)d_in[4];
    const float* b1   = (const float*)d_in[5];
    const float* Wl2  = (const float*)d_in[6];
    const float* Wr2  = (const float*)d_in[7];
    const float* att2 = (const float*)d_in[8];
    const float* b2   = (const float*)d_in[9];

    float *pxl, *pxr, *ph;
    cudaGetSymbolAddress((void**)&pxl, g_xl);
    cudaGetSymbolAddress((void**)&pxr, g_xr);
    cudaGetSymbolAddress((void**)&ph,  g_h);

    dim3 gg((NN + 127) / 128, 2 * D1 / 128);   // both Wl and Wr outputs
    const int ab = (NN * 32 + 255) / 256;      // warp per dst

    // fork: layer-1 GEMM (depends only on x/Wl1/Wr1) runs on side stream,
    // concurrent with the graph-prep chain on the main stream.
    cudaEventRecord(g_aux.e_fork, 0);
    cudaStreamWaitEvent(g_aux.s2, g_aux.e_fork, 0);
    k_gemm<<<gg, 256, 0, g_aux.s2>>>(x, Wl1, Wr1, pxl, pxr, NN, 128, D1);
    cudaEventRecord(g_aux.e_join, g_aux.s2);

    // graph prep (main stream, overlapped with GEMM1)
    k_detect_zero<<<(NN + 255) / 256, 256>>>((const unsigned*)ei);
    k_build_count<<<(NE + 255) / 256, 256>>>(ei);
    k_scan1<<<SCAN_NB, SCAN_CH>>>();
    k_scan2<<<1, 256>>>();
    k_scan3<<<(NN + 255) / 256, 256>>>();
    k_scatter<<<(NE + 255) / 256, 256>>>();

    // join: fused layer 1 needs both GEMM1 outputs and the CSR
    cudaStreamWaitEvent(0, g_aux.e_join, 0);
    k_fused<0><<<ab, 256>>>(pxl, pxr, att1, b1, ph);

    // layer 2 (serial dependence)
    k_gemm<<<gg, 256>>>(ph, Wl2, Wr2, pxl, pxr, NN, 256, D1);
    k_fused<1><<<ab, 256>>>(pxl, pxr, att2, b2, (float*)d_out);
}